// round 5
// baseline (speedup 1.0000x reference)
#include <cuda_runtime.h>
#include <cstdint>
#include <cstddef>

#define DM 1024
#define NH 16
#define DK 64
#define BB 2
#define SSEQ 2048
#define MTOT (BB*SSEQ)     // 4096
#define BH (BB*NH)         // 32

// Scratch (__device__ globals; allocation-free rule)
__device__ float g_q[(size_t)BH*SSEQ*DK];        // [B,H,S,dk]   tf32
__device__ float g_k[(size_t)BH*SSEQ*DK];        // [B,H,S,dk]   tf32
__device__ float g_vT[(size_t)BH*DK*SSEQ];       // [B,H,dk,S]   tf32
__device__ float g_attn[(size_t)MTOT*DM];        // merged [B,S,D] fp32
__device__ uint32_t g_mbits[(size_t)BB*SSEQ*(SSEQ/32)];   // 1MB bitmask

// ---------------------------------------------------------------------------
__device__ __forceinline__ uint32_t f2tf32(float x) {
    uint32_t r;
    asm("cvt.rna.tf32.f32 %0, %1;\n" : "=r"(r) : "f"(x));
    return r;
}
__device__ __forceinline__ uint4 cvt4(float4 v) {
    uint4 r;
    r.x = f2tf32(v.x); r.y = f2tf32(v.y); r.z = f2tf32(v.z); r.w = f2tf32(v.w);
    return r;
}
__device__ __forceinline__ void mma_tf32(float* c, const uint32_t* a, const uint32_t* b) {
    asm volatile(
        "mma.sync.aligned.m16n8k8.row.col.f32.tf32.tf32.f32 "
        "{%0,%1,%2,%3}, {%4,%5,%6,%7}, {%8,%9}, {%0,%1,%2,%3};\n"
        : "+f"(c[0]), "+f"(c[1]), "+f"(c[2]), "+f"(c[3])
        : "r"(a[0]), "r"(a[1]), "r"(a[2]), "r"(a[3]), "r"(b[0]), "r"(b[1]));
}
__device__ __forceinline__ void cp16(uint32_t d, const void* s) {
    asm volatile("cp.async.ca.shared.global [%0], [%1], 16;\n" :: "r"(d), "l"(s));
}
__device__ __forceinline__ void cp_commit() { asm volatile("cp.async.commit_group;\n"); }
template<int N> __device__ __forceinline__ void cp_wait() {
    asm volatile("cp.async.wait_group %0;\n" :: "n"(N));
}

// ---------------------------------------------------------------------------
// mask -> bitmask
// ---------------------------------------------------------------------------
__global__ void maskbits_kernel(const unsigned char* __restrict__ mask)
{
    const int idx = blockIdx.x * 256 + threadIdx.x;
    const uint32_t* src = (const uint32_t*)(mask + (size_t)idx * 32);
    uint32_t w = 0;
#pragma unroll
    for (int q = 0; q < 8; q++) {
        const uint32_t v = src[q];
        if (v & 0x000000ffu) w |= 1u << (q * 4 + 0);
        if (v & 0x0000ff00u) w |= 1u << (q * 4 + 1);
        if (v & 0x00ff0000u) w |= 1u << (q * 4 + 2);
        if (v & 0xff000000u) w |= 1u << (q * 4 + 3);
    }
    g_mbits[idx] = w;
}

// ---------------------------------------------------------------------------
// Projection GEMM.  k-slot permutation sigma(t)=2t, sigma(t+4)=2t+1 ->
// all fragment pairs are adjacent words -> LDS.64.
// ---------------------------------------------------------------------------
__global__ void __launch_bounds__(256) proj_tf32(
    const float* __restrict__ A, const float* __restrict__ W,
    const float* __restrict__ bias, float* __restrict__ out, int mode)
{
    __shared__ uint32_t As[128][20];
    __shared__ uint32_t Bs[128][20];
    const int tid = threadIdx.x;
    const int m0 = blockIdx.y * 128, n0 = blockIdx.x * 128;
    const int lane = tid & 31, warp = tid >> 5;
    const int wm = (warp & 3) * 32, wn = (warp >> 2) * 64;
    const int g = lane >> 2, t = lane & 3;
    const int lr = tid >> 2;
    const int lk = (tid & 3) * 4;

    const float* Ab = A + (size_t)(m0 + lr) * 1024 + lk;
    const float* Wb = W + (size_t)(n0 + lr) * 1024 + lk;

    float4 ra0 = *(const float4*)(Ab);
    float4 ra1 = *(const float4*)(Ab + (size_t)64 * 1024);
    float4 rb0 = *(const float4*)(Wb);
    float4 rb1 = *(const float4*)(Wb + (size_t)64 * 1024);

    float c[2][8][4] = {};

    for (int k0 = 16; k0 <= 1024; k0 += 16) {
        *(uint4*)&As[lr][lk]      = cvt4(ra0);
        *(uint4*)&As[lr + 64][lk] = cvt4(ra1);
        *(uint4*)&Bs[lr][lk]      = cvt4(rb0);
        *(uint4*)&Bs[lr + 64][lk] = cvt4(rb1);
        __syncthreads();
        if (k0 < 1024) {
            ra0 = *(const float4*)(Ab + k0);
            ra1 = *(const float4*)(Ab + (size_t)64 * 1024 + k0);
            rb0 = *(const float4*)(Wb + k0);
            rb1 = *(const float4*)(Wb + (size_t)64 * 1024 + k0);
        }
#pragma unroll
        for (int ks = 0; ks < 2; ks++) {
            const int kb = ks * 8 + 2 * t;
            uint32_t af[2][4], bf[8][2];
#pragma unroll
            for (int mi = 0; mi < 2; mi++) {
                const int r = wm + mi * 16 + g;
                const uint2 x = *(const uint2*)&As[r][kb];
                const uint2 y = *(const uint2*)&As[r + 8][kb];
                af[mi][0] = x.x; af[mi][2] = x.y;
                af[mi][1] = y.x; af[mi][3] = y.y;
            }
#pragma unroll
            for (int ni = 0; ni < 8; ni++) {
                const uint2 z = *(const uint2*)&Bs[wn + ni * 8 + g][kb];
                bf[ni][0] = z.x; bf[ni][1] = z.y;
            }
#pragma unroll
            for (int mi = 0; mi < 2; mi++)
#pragma unroll
                for (int ni = 0; ni < 8; ni++)
                    mma_tf32(c[mi][ni], af[mi], bf[ni]);
        }
        __syncthreads();
    }

#pragma unroll
    for (int mi = 0; mi < 2; mi++) {
#pragma unroll
        for (int rr = 0; rr < 2; rr++) {
            const int m = m0 + wm + mi * 16 + g + rr * 8;
            const int b_ = m >> 11, s = m & 2047;
#pragma unroll
            for (int ni = 0; ni < 8; ni++) {
                const int n = n0 + wn + ni * 8 + 2 * t;
                float v0 = c[mi][ni][rr * 2 + 0] + bias[n];
                float v1 = c[mi][ni][rr * 2 + 1] + bias[n + 1];
                if (mode == 0) {
                    *(float2*)&out[(size_t)m * 1024 + n] = make_float2(v0, v1);
                } else {
                    v0 = __uint_as_float(f2tf32(v0));
                    v1 = __uint_as_float(f2tf32(v1));
                    const int h = n >> 6, d = n & 63;
                    if (mode == 1) {
                        *(float2*)&out[(((size_t)(b_ * 16 + h) * 2048 + s) << 6) + d] =
                            make_float2(v0, v1);
                    } else {
                        out[((size_t)(b_ * 16 + h) * 64 + d) * 2048 + s] = v0;
                        out[((size_t)(b_ * 16 + h) * 64 + d + 1) * 2048 + s] = v1;
                    }
                }
            }
        }
    }
}

// ---------------------------------------------------------------------------
// Fused attention v3.  k-slot permutation everywhere:
//  - qk fragments via LDS.64
//  - PV a-frags = QK c-frags directly (a0,a1,a2,a3 = c0,c2,c1,c3); no shuffles
//  - PV V b-frags via LDS.64
// ---------------------------------------------------------------------------
#define CK 64
#define NCH (SSEQ/CK)         // 32
#define KW 68
#define SM_Q  0               // 128*68 = 8704 words
#define SM_K0 8704
#define SM_K1 13056
#define SM_V0 17408
#define SM_V1 21760
#define FA_SMEM_WORDS 26112
#define FA_SMEM_BYTES (FA_SMEM_WORDS*4)   // 104448

__global__ void __launch_bounds__(256, 2) fused_attn(float* __restrict__ P)
{
    extern __shared__ uint32_t sm[];
    const int tid = threadIdx.x;
    const int lane = tid & 31, warp = tid >> 5;
    const int g = lane >> 2, t = lane & 3;
    const int bh = blockIdx.y;
    const int i0 = blockIdx.x * 128;
    const int b_ = bh >> 4, h = bh & 15;
    const int wm = warp * 16;

    const float* Qg = g_q + (size_t)bh * SSEQ * DK;
    const float* Kg = g_k + (size_t)bh * SSEQ * DK;
    const float* Vg = g_vT + (size_t)bh * DK * SSEQ;
    float* Pg = P + (size_t)bh * SSEQ * SSEQ;
    const int row0 = i0 + wm + g;
    const uint32_t* mb0 = g_mbits + ((size_t)b_ * SSEQ + row0) * 64;
    const uint32_t* mb1 = mb0 + (size_t)8 * 64;

    const uint32_t sbase = (uint32_t)__cvta_generic_to_shared(sm);

    auto stageK = [&](int c) {
        const uint32_t dbase = sbase + ((c & 1) ? SM_K1 : SM_K0) * 4;
        const float* src = Kg + (size_t)c * CK * DK;
#pragma unroll
        for (int s = 0; s < 4; s++) {
            const int idx = tid + s * 256;
            const int key = idx >> 4, q = idx & 15;
            cp16(dbase + (uint32_t)(key * KW + q * 4) * 4, src + key * DK + q * 4);
        }
    };
    auto stageV = [&](int c) {
        const uint32_t dbase = sbase + ((c & 1) ? SM_V1 : SM_V0) * 4;
#pragma unroll
        for (int s = 0; s < 4; s++) {
            const int idx = tid + s * 256;
            const int d = idx >> 4, q = idx & 15;
            cp16(dbase + (uint32_t)(d * KW + q * 4) * 4,
                 Vg + (size_t)d * SSEQ + c * CK + q * 4);
        }
    };

    // stage Q once (128 x 64)
    {
#pragma unroll
        for (int s = 0; s < 8; s++) {
            const int idx = tid + s * 256;
            const int r = idx >> 4, q = idx & 15;
            cp16(sbase + (uint32_t)(SM_Q + r * KW + q * 4) * 4,
                 Qg + (size_t)(i0 + r) * DK + q * 4);
        }
        cp_commit();
    }

    const uint32_t* Qs = sm + SM_Q + (size_t)(wm + g) * KW;

    // QK^T: 16 rows x 64 keys; LDS.64 fragments via slot permutation
    auto qk = [&](const uint32_t* Kb, float cc[8][4]) {
#pragma unroll
        for (int ks = 0; ks < 8; ks++) {
            const int kb = ks * 8 + 2 * t;
            const uint2 qa = *(const uint2*)&Qs[kb];
            const uint2 qb = *(const uint2*)&Qs[8 * KW + kb];
            uint32_t a[4] = { qa.x, qb.x, qa.y, qb.y };
#pragma unroll
            for (int nt = 0; nt < 8; nt++) {
                const uint2 kv = *(const uint2*)&Kb[(nt * 8 + g) * KW + kb];
                uint32_t bb[2] = { kv.x, kv.y };
                mma_tf32(cc[nt], a, bb);
            }
        }
    };

    // ================= PASS A: row sums =================
    float l0 = 0.f, l1 = 0.f;
    stageK(0); cp_commit();
    for (int c = 0; c < NCH; c++) {
        if (c + 1 < NCH) { stageK(c + 1); cp_commit(); cp_wait<1>(); }
        else             { cp_wait<0>(); }
        __syncthreads();
        const uint32_t* Kb = sm + ((c & 1) ? SM_K1 : SM_K0);
        float cc[8][4] = {};
        qk(Kb, cc);
        const uint2 w0 = *(const uint2*)(mb0 + c * 2);
        const uint2 w1 = *(const uint2*)(mb1 + c * 2);
#pragma unroll
        for (int nt = 0; nt < 8; nt++) {
            const int sh = (nt * 8) & 31;
            const uint32_t m0w = (nt < 4) ? w0.x : w0.y;
            const uint32_t m1w = (nt < 4) ? w1.x : w1.y;
            l0 += ((m0w >> (sh + 2 * t))     & 1) ? 0.f : __expf(cc[nt][0] * 0.125f);
            l0 += ((m0w >> (sh + 2 * t + 1)) & 1) ? 0.f : __expf(cc[nt][1] * 0.125f);
            l1 += ((m1w >> (sh + 2 * t))     & 1) ? 0.f : __expf(cc[nt][2] * 0.125f);
            l1 += ((m1w >> (sh + 2 * t + 1)) & 1) ? 0.f : __expf(cc[nt][3] * 0.125f);
        }
        __syncthreads();
    }
    l0 += __shfl_xor_sync(0xffffffffu, l0, 1);
    l0 += __shfl_xor_sync(0xffffffffu, l0, 2);
    l1 += __shfl_xor_sync(0xffffffffu, l1, 1);
    l1 += __shfl_xor_sync(0xffffffffu, l1, 2);
    const float inv0 = 1.f / l0, inv1 = 1.f / l1;

    // ================= PASS B: normalize + write P + PV =================
    float oacc[8][4] = {};
    stageK(0); stageV(0); cp_commit();
    for (int c = 0; c < NCH; c++) {
        if (c + 1 < NCH) { stageK(c + 1); stageV(c + 1); cp_commit(); cp_wait<1>(); }
        else             { cp_wait<0>(); }
        __syncthreads();
        const uint32_t* Kb = sm + ((c & 1) ? SM_K1 : SM_K0);
        const uint32_t* Vb = sm + ((c & 1) ? SM_V1 : SM_V0);
        float cc[8][4] = {};
        qk(Kb, cc);
        const int jc = c * CK;
        const uint2 w0 = *(const uint2*)(mb0 + c * 2);
        const uint2 w1 = *(const uint2*)(mb1 + c * 2);
#pragma unroll
        for (int nt = 0; nt < 8; nt++) {
            const int sh = (nt * 8) & 31;
            const uint32_t m0w = (nt < 4) ? w0.x : w0.y;
            const uint32_t m1w = (nt < 4) ? w1.x : w1.y;
            cc[nt][0] = ((m0w >> (sh + 2 * t))     & 1) ? 0.f : __expf(cc[nt][0] * 0.125f) * inv0;
            cc[nt][1] = ((m0w >> (sh + 2 * t + 1)) & 1) ? 0.f : __expf(cc[nt][1] * 0.125f) * inv0;
            cc[nt][2] = ((m1w >> (sh + 2 * t))     & 1) ? 0.f : __expf(cc[nt][2] * 0.125f) * inv1;
            cc[nt][3] = ((m1w >> (sh + 2 * t + 1)) & 1) ? 0.f : __expf(cc[nt][3] * 0.125f) * inv1;
            *(float2*)&Pg[(size_t)row0 * SSEQ + jc + nt * 8 + 2 * t] =
                make_float2(cc[nt][0], cc[nt][1]);
            *(float2*)&Pg[(size_t)(row0 + 8) * SSEQ + jc + nt * 8 + 2 * t] =
                make_float2(cc[nt][2], cc[nt][3]);
        }
        // PV: a-frags directly from c-frags (slot permutation), V via LDS.64
#pragma unroll
        for (int ks = 0; ks < 8; ks++) {
            uint32_t a[4] = { f2tf32(cc[ks][0]), f2tf32(cc[ks][2]),
                              f2tf32(cc[ks][1]), f2tf32(cc[ks][3]) };
            const int kb = ks * 8 + 2 * t;
#pragma unroll
            for (int nt = 0; nt < 8; nt++) {
                const uint2 vv = *(const uint2*)&Vb[(nt * 8 + g) * KW + kb];
                uint32_t bb[2] = { vv.x, vv.y };
                mma_tf32(oacc[nt], a, bb);
            }
        }
        __syncthreads();
    }

    // epilogue: merged attn [B,S,H*64]
#pragma unroll
    for (int nt = 0; nt < 8; nt++) {
        const int d = h * 64 + nt * 8 + 2 * t;
        *(float2*)&g_attn[(size_t)(b_ * SSEQ + row0) * DM + d] =
            make_float2(oacc[nt][0], oacc[nt][1]);
        *(float2*)&g_attn[(size_t)(b_ * SSEQ + row0 + 8) * DM + d] =
            make_float2(oacc[nt][2], oacc[nt][3]);
    }
}

// ---------------------------------------------------------------------------
extern "C" void kernel_launch(void* const* d_in, const int* in_sizes, int n_in,
                              void* d_out, int out_size)
{
    const float* Q   = (const float*)d_in[0];
    const float* K   = (const float*)d_in[1];
    const float* V   = (const float*)d_in[2];
    const unsigned char* mask = (const unsigned char*)d_in[3];
    const float* WQw = (const float*)d_in[4];
    const float* WQb = (const float*)d_in[5];
    const float* WKw = (const float*)d_in[6];
    const float* WKb = (const float*)d_in[7];
    const float* WVw = (const float*)d_in[8];
    const float* WVb = (const float*)d_in[9];
    const float* Wow = (const float*)d_in[10];
    const float* Wob = (const float*)d_in[11];

    float* out   = (float*)d_out;                       // [B,S,D]
    float* attnw = out + (size_t)MTOT * DM;             // [B,H,S,S]

    float *pq, *pk, *pv, *pa;
    cudaGetSymbolAddress((void**)&pq, g_q);
    cudaGetSymbolAddress((void**)&pk, g_k);
    cudaGetSymbolAddress((void**)&pv, g_vT);
    cudaGetSymbolAddress((void**)&pa, g_attn);

    cudaFuncSetAttribute(fused_attn, cudaFuncAttributeMaxDynamicSharedMemorySize,
                         FA_SMEM_BYTES);

    maskbits_kernel<<<(BB * SSEQ * (SSEQ / 32)) / 256, 256>>>(mask);

    proj_tf32<<<dim3(8, 32), 256>>>(Q, WQw, WQb, pq, 1);
    proj_tf32<<<dim3(8, 32), 256>>>(K, WKw, WKb, pk, 1);
    proj_tf32<<<dim3(8, 32), 256>>>(V, WVw, WVb, pv, 2);

    fused_attn<<<dim3(16, 32), 256, FA_SMEM_BYTES>>>(attnw);

    proj_tf32<<<dim3(8, 32), 256>>>(pa, Wow, Wob, out, 0);
}

// round 7
// speedup vs baseline: 1.1352x; 1.1352x over previous
#include <cuda_runtime.h>
#include <cstdint>
#include <cstddef>

#define DM 1024
#define NH 16
#define DK 64
#define BB 2
#define SSEQ 2048
#define MTOT (BB*SSEQ)     // 4096
#define BH (BB*NH)         // 32

// Scratch (__device__ globals; allocation-free rule)
// g_q, g_k: d-columns sigma-permuted within 8-groups.
// g_vT: d-rows natural, key-columns sigma-permuted.
__device__ float g_q[(size_t)BH*SSEQ*DK];
__device__ float g_k[(size_t)BH*SSEQ*DK];
__device__ float g_vT[(size_t)BH*DK*SSEQ];
__device__ float g_attn[(size_t)MTOT*DM];
__device__ uint32_t g_mbits[(size_t)BB*SSEQ*(SSEQ/32)];

// ---------------------------------------------------------------------------
__device__ __forceinline__ uint32_t f2tf32(float x) {
    uint32_t r;
    asm("cvt.rna.tf32.f32 %0, %1;\n" : "=r"(r) : "f"(x));
    return r;
}
__device__ __forceinline__ void mma_tf32(float* c, const uint32_t* a, const uint32_t* b) {
    asm volatile(
        "mma.sync.aligned.m16n8k8.row.col.f32.tf32.tf32.f32 "
        "{%0,%1,%2,%3}, {%4,%5,%6,%7}, {%8,%9}, {%0,%1,%2,%3};\n"
        : "+f"(c[0]), "+f"(c[1]), "+f"(c[2]), "+f"(c[3])
        : "r"(a[0]), "r"(a[1]), "r"(a[2]), "r"(a[3]), "r"(b[0]), "r"(b[1]));
}
__device__ __forceinline__ void cp16(uint32_t d, const void* s) {
    asm volatile("cp.async.ca.shared.global [%0], [%1], 16;\n" :: "r"(d), "l"(s));
}
__device__ __forceinline__ void cp_commit() { asm volatile("cp.async.commit_group;\n"); }
template<int N> __device__ __forceinline__ void cp_wait() {
    asm volatile("cp.async.wait_group %0;\n" :: "n"(N));
}
// sigma(l): phys position holding logical l within an 8-group
__device__ __host__ __forceinline__ int sigma8(int l) {
    return (l < 4) ? 2 * l : 2 * (l - 4) + 1;
}

// ---------------------------------------------------------------------------
// mask -> bitmask
// ---------------------------------------------------------------------------
__global__ void maskbits_kernel(const unsigned char* __restrict__ mask)
{
    const int idx = blockIdx.x * 256 + threadIdx.x;
    const uint32_t* src = (const uint32_t*)(mask + (size_t)idx * 32);
    uint32_t w = 0;
#pragma unroll
    for (int q = 0; q < 8; q++) {
        const uint32_t v = src[q];
        if (v & 0x000000ffu) w |= 1u << (q * 4 + 0);
        if (v & 0x0000ff00u) w |= 1u << (q * 4 + 1);
        if (v & 0x00ff0000u) w |= 1u << (q * 4 + 2);
        if (v & 0xff000000u) w |= 1u << (q * 4 + 3);
    }
    g_mbits[idx] = w;
}

// ---------------------------------------------------------------------------
// Projection GEMM.  Smem k-columns stored sigma-permuted (pair-transpose STS.64);
// fragment loads = conflict-free LDS.64 at stride 24.
// mode 0: fp32 out[m][n]
// mode 1: tf32 split-heads [bh,s,64], d-columns sigma-permuted
// mode 2: tf32 V^T [bh,64,s], d-rows NATURAL, s-columns sigma-permuted
// ---------------------------------------------------------------------------
__global__ void __launch_bounds__(256) proj_tf32(
    const float* __restrict__ A, const float* __restrict__ W,
    const float* __restrict__ bias, float* __restrict__ out, int mode)
{
    __shared__ uint32_t As[128][24];
    __shared__ uint32_t Bs[128][24];
    const int tid = threadIdx.x;
    const int m0 = blockIdx.y * 128, n0 = blockIdx.x * 128;
    const int lane = tid & 31, warp = tid >> 5;
    const int wm = (warp & 3) * 32, wn = (warp >> 2) * 64;
    const int g = lane >> 2, t = lane & 3;
    const int row = tid >> 1;            // 0..127
    const int kh = (tid & 1) * 8;        // 0 or 8

    const float* Ab = A + (size_t)(m0 + row) * 1024 + kh;
    const float* Wb = W + (size_t)(n0 + row) * 1024 + kh;

    float4 ra0 = *(const float4*)(Ab);
    float4 ra1 = *(const float4*)(Ab + 4);
    float4 rb0 = *(const float4*)(Wb);
    float4 rb1 = *(const float4*)(Wb + 4);

    float c[2][8][4] = {};

    for (int k0 = 16; k0 <= 1024; k0 += 16) {
        // pair-transpose store: phys (2j, 2j+1) = (logical j, logical j+4)
        {
            uint2 w0 = { f2tf32(ra0.x), f2tf32(ra1.x) };
            uint2 w1 = { f2tf32(ra0.y), f2tf32(ra1.y) };
            uint2 w2 = { f2tf32(ra0.z), f2tf32(ra1.z) };
            uint2 w3 = { f2tf32(ra0.w), f2tf32(ra1.w) };
            *(uint2*)&As[row][kh + 0] = w0;
            *(uint2*)&As[row][kh + 2] = w1;
            *(uint2*)&As[row][kh + 4] = w2;
            *(uint2*)&As[row][kh + 6] = w3;
            uint2 v0 = { f2tf32(rb0.x), f2tf32(rb1.x) };
            uint2 v1 = { f2tf32(rb0.y), f2tf32(rb1.y) };
            uint2 v2 = { f2tf32(rb0.z), f2tf32(rb1.z) };
            uint2 v3 = { f2tf32(rb0.w), f2tf32(rb1.w) };
            *(uint2*)&Bs[row][kh + 0] = v0;
            *(uint2*)&Bs[row][kh + 2] = v1;
            *(uint2*)&Bs[row][kh + 4] = v2;
            *(uint2*)&Bs[row][kh + 6] = v3;
        }
        __syncthreads();
        if (k0 < 1024) {
            ra0 = *(const float4*)(Ab + k0);
            ra1 = *(const float4*)(Ab + k0 + 4);
            rb0 = *(const float4*)(Wb + k0);
            rb1 = *(const float4*)(Wb + k0 + 4);
        }
#pragma unroll
        for (int ks = 0; ks < 2; ks++) {
            const int kb = ks * 8 + 2 * t;
            uint32_t af[2][4], bf[8][2];
#pragma unroll
            for (int mi = 0; mi < 2; mi++) {
                const int r = wm + mi * 16 + g;
                const uint2 x = *(const uint2*)&As[r][kb];
                const uint2 y = *(const uint2*)&As[r + 8][kb];
                af[mi][0] = x.x; af[mi][2] = x.y;
                af[mi][1] = y.x; af[mi][3] = y.y;
            }
#pragma unroll
            for (int ni = 0; ni < 8; ni++) {
                const uint2 z = *(const uint2*)&Bs[wn + ni * 8 + g][kb];
                bf[ni][0] = z.x; bf[ni][1] = z.y;
            }
#pragma unroll
            for (int mi = 0; mi < 2; mi++)
#pragma unroll
                for (int ni = 0; ni < 8; ni++)
                    mma_tf32(c[mi][ni], af[mi], bf[ni]);
        }
        __syncthreads();
    }

    // logical n columns this thread holds in the 8-group: 2t and 2t+1
    const int p0 = (t < 2) ? 4 * t : 4 * t - 7;       // sigma(2t)
    const int p1 = (t < 2) ? 4 * t + 2 : 4 * t - 5;   // sigma(2t+1)

#pragma unroll
    for (int mi = 0; mi < 2; mi++) {
#pragma unroll
        for (int rr = 0; rr < 2; rr++) {
            const int m = m0 + wm + mi * 16 + g + rr * 8;
            const int b_ = m >> 11, s = m & 2047;
#pragma unroll
            for (int ni = 0; ni < 8; ni++) {
                const int n = n0 + wn + ni * 8 + 2 * t;
                float v0 = c[mi][ni][rr * 2 + 0] + bias[n];
                float v1 = c[mi][ni][rr * 2 + 1] + bias[n + 1];
                if (mode == 0) {
                    *(float2*)&out[(size_t)m * 1024 + n] = make_float2(v0, v1);
                } else {
                    v0 = __uint_as_float(f2tf32(v0));
                    v1 = __uint_as_float(f2tf32(v1));
                    const int h = n >> 6;
                    const int dbase = (n & 63) & ~7;
                    if (mode == 1) {
                        // d-columns sigma-permuted
                        float* o = out + (((size_t)(b_ * 16 + h) * 2048 + s) << 6) + dbase;
                        o[p0] = v0;
                        o[p1] = v1;
                    } else {
                        // vT: d-rows NATURAL (2t, 2t+1); s-columns sigma-permuted
                        const int sp = (s & ~7) | sigma8(s & 7);
                        out[((size_t)(b_ * 16 + h) * 64 + dbase + 2 * t) * 2048 + sp] = v0;
                        out[((size_t)(b_ * 16 + h) * 64 + dbase + 2 * t + 1) * 2048 + sp] = v1;
                    }
                }
            }
        }
    }
}

// ---------------------------------------------------------------------------
// Fused attention v4.  Stride-72 smem (LDS.64 conflict-free).
// K rows sigma-permuted at staging; Q/K d-cols and V key-cols pre-permuted.
// PV a-frags taken directly from QK c-frags.  No shuffles in hot loop.
// ---------------------------------------------------------------------------
#define CK 64
#define NCH (SSEQ/CK)         // 32
#define KW 72
#define SM_Q  0               // 128*72 = 9216 words
#define SM_K0 9216
#define SM_K1 13824
#define SM_V0 18432
#define SM_V1 23040
#define FA_SMEM_WORDS 27648
#define FA_SMEM_BYTES (FA_SMEM_WORDS*4)   // 110592

__global__ void __launch_bounds__(256, 2) fused_attn(float* __restrict__ P)
{
    extern __shared__ uint32_t sm[];
    const int tid = threadIdx.x;
    const int lane = tid & 31, warp = tid >> 5;
    const int g = lane >> 2, t = lane & 3;
    const int bh = blockIdx.y;
    const int i0 = blockIdx.x * 128;
    const int b_ = bh >> 4, h = bh & 15;
    const int wm = warp * 16;

    const float* Qg = g_q + (size_t)bh * SSEQ * DK;
    const float* Kg = g_k + (size_t)bh * SSEQ * DK;
    const float* Vg = g_vT + (size_t)bh * DK * SSEQ;
    float* Pg = P + (size_t)bh * SSEQ * SSEQ;
    const int row0 = i0 + wm + g;
    const uint32_t* mb0 = g_mbits + ((size_t)b_ * SSEQ + row0) * 64;
    const uint32_t* mb1 = mb0 + (size_t)8 * 64;

    const uint32_t sbase = (uint32_t)__cvta_generic_to_shared(sm);

    // K rows permuted at staging destination (keys within 8-groups)
    auto stageK = [&](int c) {
        const uint32_t dbase = sbase + ((c & 1) ? SM_K1 : SM_K0) * 4;
        const float* src = Kg + (size_t)c * CK * DK;
#pragma unroll
        for (int s = 0; s < 4; s++) {
            const int idx = tid + s * 256;
            const int key = idx >> 4, q = idx & 15;
            const int rp = (key & ~7) | sigma8(key & 7);
            cp16(dbase + (uint32_t)(rp * KW + q * 4) * 4, src + key * DK + q * 4);
        }
    };
    auto stageV = [&](int c) {
        const uint32_t dbase = sbase + ((c & 1) ? SM_V1 : SM_V0) * 4;
#pragma unroll
        for (int s = 0; s < 4; s++) {
            const int idx = tid + s * 256;
            const int d = idx >> 4, q = idx & 15;
            cp16(dbase + (uint32_t)(d * KW + q * 4) * 4,
                 Vg + (size_t)d * SSEQ + c * CK + q * 4);
        }
    };

    // stage Q once (rows natural; d-cols already permuted in g_q)
    {
#pragma unroll
        for (int s = 0; s < 8; s++) {
            const int idx = tid + s * 256;
            const int r = idx >> 4, q = idx & 15;
            cp16(sbase + (uint32_t)(SM_Q + r * KW + q * 4) * 4,
                 Qg + (size_t)(i0 + r) * DK + q * 4);
        }
        cp_commit();
    }

    const uint32_t* Qs = sm + SM_Q + (size_t)(wm + g) * KW;

    // QK^T: LDS.64 fragments, conflict-free at stride 72
    auto qk = [&](const uint32_t* Kb, float cc[8][4]) {
#pragma unroll
        for (int ks = 0; ks < 8; ks++) {
            const int kb = ks * 8 + 2 * t;
            const uint2 qa = *(const uint2*)&Qs[kb];
            const uint2 qb = *(const uint2*)&Qs[8 * KW + kb];
            uint32_t a[4] = { qa.x, qb.x, qa.y, qb.y };
#pragma unroll
            for (int nt = 0; nt < 8; nt++) {
                const uint2 kv = *(const uint2*)&Kb[(nt * 8 + g) * KW + kb];
                uint32_t bb[2] = { kv.x, kv.y };
                mma_tf32(cc[nt], a, bb);
            }
        }
    };

    // ================= PASS A: row sums =================
    // c-frag col (phys 2t,2t+1) = logical keys (t, t+4) due to K-row permutation
    float l0 = 0.f, l1 = 0.f;
    stageK(0); cp_commit();
    for (int c = 0; c < NCH; c++) {
        if (c + 1 < NCH) { stageK(c + 1); cp_commit(); cp_wait<1>(); }
        else             { cp_wait<0>(); }
        __syncthreads();
        const uint32_t* Kb = sm + ((c & 1) ? SM_K1 : SM_K0);
        float cc[8][4] = {};
        qk(Kb, cc);
        const uint2 w0 = *(const uint2*)(mb0 + c * 2);
        const uint2 w1 = *(const uint2*)(mb1 + c * 2);
#pragma unroll
        for (int nt = 0; nt < 8; nt++) {
            const int sh = (nt * 8) & 31;
            const uint32_t m0w = (nt < 4) ? w0.x : w0.y;
            const uint32_t m1w = (nt < 4) ? w1.x : w1.y;
            l0 += ((m0w >> (sh + t))     & 1) ? 0.f : __expf(cc[nt][0] * 0.125f);
            l0 += ((m0w >> (sh + t + 4)) & 1) ? 0.f : __expf(cc[nt][1] * 0.125f);
            l1 += ((m1w >> (sh + t))     & 1) ? 0.f : __expf(cc[nt][2] * 0.125f);
            l1 += ((m1w >> (sh + t + 4)) & 1) ? 0.f : __expf(cc[nt][3] * 0.125f);
        }
        __syncthreads();
    }
    l0 += __shfl_xor_sync(0xffffffffu, l0, 1);
    l0 += __shfl_xor_sync(0xffffffffu, l0, 2);
    l1 += __shfl_xor_sync(0xffffffffu, l1, 1);
    l1 += __shfl_xor_sync(0xffffffffu, l1, 2);
    const float inv0 = 1.f / l0, inv1 = 1.f / l1;

    // ================= PASS B: normalize + write P + PV =================
    float oacc[8][4] = {};
    stageK(0); stageV(0); cp_commit();
    for (int c = 0; c < NCH; c++) {
        if (c + 1 < NCH) { stageK(c + 1); stageV(c + 1); cp_commit(); cp_wait<1>(); }
        else             { cp_wait<0>(); }
        __syncthreads();
        const uint32_t* Kb = sm + ((c & 1) ? SM_K1 : SM_K0);
        const uint32_t* Vb = sm + ((c & 1) ? SM_V1 : SM_V0);
        float cc[8][4] = {};
        qk(Kb, cc);
        const int jc = c * CK;
        const uint2 w0 = *(const uint2*)(mb0 + c * 2);
        const uint2 w1 = *(const uint2*)(mb1 + c * 2);
#pragma unroll
        for (int nt = 0; nt < 8; nt++) {
            const int sh = (nt * 8) & 31;
            const uint32_t m0w = (nt < 4) ? w0.x : w0.y;
            const uint32_t m1w = (nt < 4) ? w1.x : w1.y;
            cc[nt][0] = ((m0w >> (sh + t))     & 1) ? 0.f : __expf(cc[nt][0] * 0.125f) * inv0;
            cc[nt][1] = ((m0w >> (sh + t + 4)) & 1) ? 0.f : __expf(cc[nt][1] * 0.125f) * inv0;
            cc[nt][2] = ((m1w >> (sh + t))     & 1) ? 0.f : __expf(cc[nt][2] * 0.125f) * inv1;
            cc[nt][3] = ((m1w >> (sh + t + 4)) & 1) ? 0.f : __expf(cc[nt][3] * 0.125f) * inv1;
            // P stores at logical key columns t and t+4
            float* pr0 = &Pg[(size_t)row0 * SSEQ + jc + nt * 8];
            float* pr1 = &Pg[(size_t)(row0 + 8) * SSEQ + jc + nt * 8];
            pr0[t]     = cc[nt][0];
            pr0[t + 4] = cc[nt][1];
            pr1[t]     = cc[nt][2];
            pr1[t + 4] = cc[nt][3];
        }
        // PV: a-frags directly from c-frags; V key-cols permuted to match
#pragma unroll
        for (int ks = 0; ks < 8; ks++) {
            uint32_t a[4] = { f2tf32(cc[ks][0]), f2tf32(cc[ks][2]),
                              f2tf32(cc[ks][1]), f2tf32(cc[ks][3]) };
            const int kb = ks * 8 + 2 * t;
#pragma unroll
            for (int nt = 0; nt < 8; nt++) {
                const uint2 vv = *(const uint2*)&Vb[(nt * 8 + g) * KW + kb];
                uint32_t bb[2] = { vv.x, vv.y };
                mma_tf32(oacc[nt], a, bb);
            }
        }
        __syncthreads();
    }

    // epilogue: merged attn [B,S,H*64]; V d-rows natural -> cols 2t,2t+1
#pragma unroll
    for (int nt = 0; nt < 8; nt++) {
        const int d = h * 64 + nt * 8 + 2 * t;
        *(float2*)&g_attn[(size_t)(b_ * SSEQ + row0) * DM + d] =
            make_float2(oacc[nt][0], oacc[nt][1]);
        *(float2*)&g_attn[(size_t)(b_ * SSEQ + row0 + 8) * DM + d] =
            make_float2(oacc[nt][2], oacc[nt][3]);
    }
}

// ---------------------------------------------------------------------------
extern "C" void kernel_launch(void* const* d_in, const int* in_sizes, int n_in,
                              void* d_out, int out_size)
{
    const float* Q   = (const float*)d_in[0];
    const float* K   = (const float*)d_in[1];
    const float* V   = (const float*)d_in[2];
    const unsigned char* mask = (const unsigned char*)d_in[3];
    const float* WQw = (const float*)d_in[4];
    const float* WQb = (const float*)d_in[5];
    const float* WKw = (const float*)d_in[6];
    const float* WKb = (const float*)d_in[7];
    const float* WVw = (const float*)d_in[8];
    const float* WVb = (const float*)d_in[9];
    const float* Wow = (const float*)d_in[10];
    const float* Wob = (const float*)d_in[11];

    float* out   = (float*)d_out;                       // [B,S,D]
    float* attnw = out + (size_t)MTOT * DM;             // [B,H,S,S]

    float *pq, *pk, *pv, *pa;
    cudaGetSymbolAddress((void**)&pq, g_q);
    cudaGetSymbolAddress((void**)&pk, g_k);
    cudaGetSymbolAddress((void**)&pv, g_vT);
    cudaGetSymbolAddress((void**)&pa, g_attn);

    cudaFuncSetAttribute(fused_attn, cudaFuncAttributeMaxDynamicSharedMemorySize,
                         FA_SMEM_BYTES);

    maskbits_kernel<<<(BB * SSEQ * (SSEQ / 32)) / 256, 256>>>(mask);

    proj_tf32<<<dim3(8, 32), 256>>>(Q, WQw, WQb, pq, 1);
    proj_tf32<<<dim3(8, 32), 256>>>(K, WKw, WKb, pk, 1);
    proj_tf32<<<dim3(8, 32), 256>>>(V, WVw, WVb, pv, 2);

    fused_attn<<<dim3(16, 32), 256, FA_SMEM_BYTES>>>(attnw);

    proj_tf32<<<dim3(8, 32), 256>>>(pa, Wow, Wob, out, 0);
}

// round 8
// speedup vs baseline: 1.4996x; 1.3210x over previous
#include <cuda_runtime.h>
#include <cuda_fp16.h>
#include <cstdint>
#include <cstddef>

#define DM 1024
#define NH 16
#define DK 64
#define BB 2
#define SSEQ 2048
#define MTOT (BB*SSEQ)     // 4096
#define BH (BB*NH)         // 32

// Scratch (__device__ globals).  All half2-packed words (uint32).
// g_q/g_k: [bh][s][32 words], d half2-words sigma-permuted per 8-word group.
// g_vT:    [bh][64 d][1024 words], key half2-words sigma-permuted per 8-word group.
__device__ uint32_t g_q[(size_t)BH*SSEQ*32];
__device__ uint32_t g_k[(size_t)BH*SSEQ*32];
__device__ uint32_t g_vT[(size_t)BH*DK*1024];
__device__ float    g_attn[(size_t)MTOT*DM];
__device__ uint32_t g_mbits[(size_t)BB*SSEQ*(SSEQ/32)];

// ---------------------------------------------------------------------------
__device__ __forceinline__ uint32_t h2pack(float a, float b) {
    __half2 h = __floats2half2_rn(a, b);
    return *(uint32_t*)&h;
}
__device__ __forceinline__ void mma_f16(float* c, const uint32_t* a, const uint32_t* b) {
    asm volatile(
        "mma.sync.aligned.m16n8k16.row.col.f32.f16.f16.f32 "
        "{%0,%1,%2,%3}, {%4,%5,%6,%7}, {%8,%9}, {%0,%1,%2,%3};\n"
        : "+f"(c[0]), "+f"(c[1]), "+f"(c[2]), "+f"(c[3])
        : "r"(a[0]), "r"(a[1]), "r"(a[2]), "r"(a[3]), "r"(b[0]), "r"(b[1]));
}
__device__ __forceinline__ void cp16(uint32_t d, const void* s) {
    asm volatile("cp.async.ca.shared.global [%0], [%1], 16;\n" :: "r"(d), "l"(s));
}
__device__ __forceinline__ void cp_commit() { asm volatile("cp.async.commit_group;\n"); }
template<int N> __device__ __forceinline__ void cp_wait() {
    asm volatile("cp.async.wait_group %0;\n" :: "n"(N));
}
__device__ __host__ __forceinline__ int sigma8(int j) {
    return (j < 4) ? 2 * j : 2 * (j - 4) + 1;
}

// ---------------------------------------------------------------------------
__global__ void maskbits_kernel(const unsigned char* __restrict__ mask)
{
    const int idx = blockIdx.x * 256 + threadIdx.x;
    const uint32_t* src = (const uint32_t*)(mask + (size_t)idx * 32);
    uint32_t w = 0;
#pragma unroll
    for (int q = 0; q < 8; q++) {
        const uint32_t v = src[q];
        if (v & 0x000000ffu) w |= 1u << (q * 4 + 0);
        if (v & 0x0000ff00u) w |= 1u << (q * 4 + 1);
        if (v & 0x00ff0000u) w |= 1u << (q * 4 + 2);
        if (v & 0xff000000u) w |= 1u << (q * 4 + 3);
    }
    g_mbits[idx] = w;
}

// ---------------------------------------------------------------------------
// Projection GEMM, fp16 m16n8k16.  BK=32.  Smem rows: 16 half2-words,
// sigma-paired (w_j, w_{j+4}) adjacent -> frag = 1 LDS.64.  Stride 40 words.
// mode 0: fp32 out[m][n]; mode 1: g_q/g_k layout; mode 2: g_vT layout
// ---------------------------------------------------------------------------
__global__ void __launch_bounds__(256) proj_f16(
    const float* __restrict__ A, const float* __restrict__ W,
    const float* __restrict__ bias, void* __restrict__ outv, int mode)
{
    __shared__ uint32_t As[128 * 40];
    __shared__ uint32_t Bs[128 * 40];
    const int tid = threadIdx.x;
    const int m0 = blockIdx.y * 128, n0 = blockIdx.x * 128;
    const int lane = tid & 31, warp = tid >> 5;
    const int wm = (warp & 3) * 32, wn = (warp >> 2) * 64;
    const int g = lane >> 2, t = lane & 3;
    const int row = tid >> 1;            // 0..127
    const int e = tid & 1;               // which k16 tile of BK32

    const float* Ab = A + (size_t)(m0 + row) * 1024 + e * 16;
    const float* Wb = W + (size_t)(n0 + row) * 1024 + e * 16;

    float4 fa[4], fw[4];
#pragma unroll
    for (int i = 0; i < 4; i++) {
        fa[i] = *(const float4*)(Ab + i * 4);
        fw[i] = *(const float4*)(Wb + i * 4);
    }

    float c[2][8][4] = {};

    for (int k0 = 32; k0 <= 1024; k0 += 32) {
        {
            uint32_t wA[8], wW[8];
#pragma unroll
            for (int i = 0; i < 4; i++) {
                wA[2*i]   = h2pack(fa[i].x, fa[i].y);
                wA[2*i+1] = h2pack(fa[i].z, fa[i].w);
                wW[2*i]   = h2pack(fw[i].x, fw[i].y);
                wW[2*i+1] = h2pack(fw[i].z, fw[i].w);
            }
            uint32_t* da = &As[row * 40 + e * 8];
            uint32_t* dw = &Bs[row * 40 + e * 8];
#pragma unroll
            for (int j = 0; j < 4; j++) {
                *(uint2*)&da[2*j] = make_uint2(wA[j], wA[j+4]);
                *(uint2*)&dw[2*j] = make_uint2(wW[j], wW[j+4]);
            }
        }
        __syncthreads();
        if (k0 < 1024) {
#pragma unroll
            for (int i = 0; i < 4; i++) {
                fa[i] = *(const float4*)(Ab + k0 + i * 4);
                fw[i] = *(const float4*)(Wb + k0 + i * 4);
            }
        }
#pragma unroll
        for (int ks = 0; ks < 2; ks++) {
            const int kb = ks * 8 + 2 * t;
            uint32_t af[2][4], bf[8][2];
#pragma unroll
            for (int mi = 0; mi < 2; mi++) {
                const int r = wm + mi * 16 + g;
                const uint2 x = *(const uint2*)&As[r * 40 + kb];
                const uint2 y = *(const uint2*)&As[(r + 8) * 40 + kb];
                af[mi][0] = x.x; af[mi][2] = x.y;
                af[mi][1] = y.x; af[mi][3] = y.y;
            }
#pragma unroll
            for (int ni = 0; ni < 8; ni++) {
                const uint2 z = *(const uint2*)&Bs[(wn + ni * 8 + g) * 40 + kb];
                bf[ni][0] = z.x; bf[ni][1] = z.y;
            }
#pragma unroll
            for (int mi = 0; mi < 2; mi++)
#pragma unroll
                for (int ni = 0; ni < 8; ni++)
                    mma_f16(c[mi][ni], af[mi], bf[ni]);
        }
        __syncthreads();
    }

#pragma unroll
    for (int mi = 0; mi < 2; mi++) {
#pragma unroll
        for (int rr = 0; rr < 2; rr++) {
            const int m = m0 + wm + mi * 16 + g + rr * 8;
            const int b_ = m >> 11, s = m & 2047;
#pragma unroll
            for (int ni = 0; ni < 8; ni++) {
                const int n = n0 + wn + ni * 8 + 2 * t;
                const float v0 = c[mi][ni][rr * 2 + 0] + bias[n];
                const float v1 = c[mi][ni][rr * 2 + 1] + bias[n + 1];
                if (mode == 0) {
                    *(float2*)&((float*)outv)[(size_t)m * 1024 + n] = make_float2(v0, v1);
                } else if (mode == 1) {
                    // g_q/g_k: [bh][s][32 words]; word = (ni>>1)*8 + 2t + (ni&1)
                    const int h = n >> 6;
                    const int ni_l = (n & 63) >> 3;        // local ni within head
                    const int widx = (ni_l >> 1) * 8 + 2 * t + (ni_l & 1);
                    ((uint32_t*)outv)[((size_t)(b_ * 16 + h) * 2048 + s) * 32 + widx] =
                        h2pack(v0, v1);
                } else {
                    // g_vT half view: [bh][64 d][2048 keys], key words sigma'd
                    const int h = n >> 6;
                    const int dn = n & 63;
                    const int sw = (s >> 4) * 16 + sigma8((s & 15) >> 1) * 2 + (s & 1);
                    __half* vh = (__half*)outv;
                    vh[((size_t)(b_ * 16 + h) * 64 + dn) * 2048 + sw]     = __float2half_rn(v0);
                    vh[((size_t)(b_ * 16 + h) * 64 + dn + 1) * 2048 + sw] = __float2half_rn(v1);
                }
            }
        }
    }
}

// ---------------------------------------------------------------------------
// Fused attention, fp16.  CTA = 128 q-rows x (b,h), 8 warps x 16 rows.
// Q fragments in registers (16 regs, loaded once).  K/V chunks cp.async
// double-buffered, stride-40 rows.  QK c-frags chain into PV a-frags natively.
// ---------------------------------------------------------------------------
#define CK 64
#define NCH (SSEQ/CK)         // 32
#define KW 40                 // words per smem row
#define KBUF (CK*KW)          // 2560 words

__global__ void __launch_bounds__(256, 2) fused_attn(float* __restrict__ P)
{
    __shared__ uint32_t sm[4 * KBUF];    // K0 K1 V0 V1 = 40 KB
    const int tid = threadIdx.x;
    const int lane = tid & 31, warp = tid >> 5;
    const int g = lane >> 2, t = lane & 3;
    const int bh = blockIdx.y;
    const int i0 = blockIdx.x * 128;
    const int b_ = bh >> 4, h = bh & 15;
    const int wm = warp * 16;
    const int row0 = i0 + wm + g;

    const uint32_t* Kg = g_k + (size_t)bh * SSEQ * 32;
    const uint32_t* Vg = g_vT + (size_t)bh * DK * 1024;
    float* Pg = P + (size_t)bh * SSEQ * SSEQ;
    const uint32_t* mb0 = g_mbits + ((size_t)b_ * SSEQ + row0) * 64;
    const uint32_t* mb1 = mb0 + (size_t)8 * 64;

    const uint32_t sbase = (uint32_t)__cvta_generic_to_shared(sm);

    auto stageK = [&](int c) {
        const uint32_t dbase = sbase + ((c & 1) ? KBUF : 0) * 4;
        const uint32_t* src = Kg + (size_t)c * CK * 32;
#pragma unroll
        for (int s = 0; s < 2; s++) {
            const int idx = tid + s * 256;
            const int key = idx >> 3, seg = idx & 7;
            cp16(dbase + (uint32_t)(key * KW + seg * 4) * 4, src + key * 32 + seg * 4);
        }
    };
    auto stageV = [&](int c) {
        const uint32_t dbase = sbase + ((c & 1) ? 3 * KBUF : 2 * KBUF) * 4;
#pragma unroll
        for (int s = 0; s < 2; s++) {
            const int idx = tid + s * 256;
            const int d = idx >> 3, seg = idx & 7;
            cp16(dbase + (uint32_t)(d * KW + seg * 4) * 4,
                 Vg + (size_t)d * 1024 + c * 32 + seg * 4);
        }
    };

    // Q fragments -> registers, once
    uint32_t qf[4][4];
#pragma unroll
    for (int ks = 0; ks < 4; ks++) {
        const uint2 qa = *(const uint2*)&g_q[((size_t)bh * SSEQ + row0) * 32 + ks * 8 + 2 * t];
        const uint2 qb = *(const uint2*)&g_q[((size_t)bh * SSEQ + row0 + 8) * 32 + ks * 8 + 2 * t];
        qf[ks][0] = qa.x; qf[ks][2] = qa.y;
        qf[ks][1] = qb.x; qf[ks][3] = qb.y;
    }

    auto qk = [&](const uint32_t* Kb, float cc[8][4]) {
#pragma unroll
        for (int ks = 0; ks < 4; ks++) {
            const int kb = ks * 8 + 2 * t;
#pragma unroll
            for (int nt = 0; nt < 8; nt++) {
                const uint2 kv = *(const uint2*)&Kb[(nt * 8 + g) * KW + kb];
                uint32_t bb[2] = { kv.x, kv.y };
                mma_f16(cc[nt], qf[ks], bb);
            }
        }
    };

    // ================= PASS A: row sums =================
    float l0 = 0.f, l1 = 0.f;
    stageK(0); cp_commit();
    for (int c = 0; c < NCH; c++) {
        if (c + 1 < NCH) { stageK(c + 1); cp_commit(); cp_wait<1>(); }
        else             { cp_wait<0>(); }
        __syncthreads();
        const uint32_t* Kb = sm + ((c & 1) ? KBUF : 0);
        float cc[8][4] = {};
        qk(Kb, cc);
        const uint2 w0 = *(const uint2*)(mb0 + c * 2);
        const uint2 w1 = *(const uint2*)(mb1 + c * 2);
#pragma unroll
        for (int nt = 0; nt < 8; nt++) {
            const int sh = (nt * 8) & 31;
            const uint32_t m0w = (nt < 4) ? w0.x : w0.y;
            const uint32_t m1w = (nt < 4) ? w1.x : w1.y;
            l0 += ((m0w >> (sh + 2 * t))     & 1) ? 0.f : __expf(cc[nt][0] * 0.125f);
            l0 += ((m0w >> (sh + 2 * t + 1)) & 1) ? 0.f : __expf(cc[nt][1] * 0.125f);
            l1 += ((m1w >> (sh + 2 * t))     & 1) ? 0.f : __expf(cc[nt][2] * 0.125f);
            l1 += ((m1w >> (sh + 2 * t + 1)) & 1) ? 0.f : __expf(cc[nt][3] * 0.125f);
        }
        __syncthreads();
    }
    l0 += __shfl_xor_sync(0xffffffffu, l0, 1);
    l0 += __shfl_xor_sync(0xffffffffu, l0, 2);
    l1 += __shfl_xor_sync(0xffffffffu, l1, 1);
    l1 += __shfl_xor_sync(0xffffffffu, l1, 2);
    const float inv0 = 1.f / l0, inv1 = 1.f / l1;

    // ================= PASS B: normalize + write P + PV =================
    float oacc[8][4] = {};
    stageK(0); stageV(0); cp_commit();
    for (int c = 0; c < NCH; c++) {
        if (c + 1 < NCH) { stageK(c + 1); stageV(c + 1); cp_commit(); cp_wait<1>(); }
        else             { cp_wait<0>(); }
        __syncthreads();
        const uint32_t* Kb = sm + ((c & 1) ? KBUF : 0);
        const uint32_t* Vb = sm + ((c & 1) ? 3 * KBUF : 2 * KBUF);
        float cc[8][4] = {};
        qk(Kb, cc);
        const int jc = c * CK;
        const uint2 w0 = *(const uint2*)(mb0 + c * 2);
        const uint2 w1 = *(const uint2*)(mb1 + c * 2);
#pragma unroll
        for (int nt = 0; nt < 8; nt++) {
            const int sh = (nt * 8) & 31;
            const uint32_t m0w = (nt < 4) ? w0.x : w0.y;
            const uint32_t m1w = (nt < 4) ? w1.x : w1.y;
            cc[nt][0] = ((m0w >> (sh + 2 * t))     & 1) ? 0.f : __expf(cc[nt][0] * 0.125f) * inv0;
            cc[nt][1] = ((m0w >> (sh + 2 * t + 1)) & 1) ? 0.f : __expf(cc[nt][1] * 0.125f) * inv0;
            cc[nt][2] = ((m1w >> (sh + 2 * t))     & 1) ? 0.f : __expf(cc[nt][2] * 0.125f) * inv1;
            cc[nt][3] = ((m1w >> (sh + 2 * t + 1)) & 1) ? 0.f : __expf(cc[nt][3] * 0.125f) * inv1;
            *(float2*)&Pg[(size_t)row0 * SSEQ + jc + nt * 8 + 2 * t] =
                make_float2(cc[nt][0], cc[nt][1]);
            *(float2*)&Pg[(size_t)(row0 + 8) * SSEQ + jc + nt * 8 + 2 * t] =
                make_float2(cc[nt][2], cc[nt][3]);
        }
        // PV: a-frags packed straight from c-frags (natural layout)
#pragma unroll
        for (int ks = 0; ks < 4; ks++) {
            uint32_t a[4] = {
                h2pack(cc[2*ks][0],   cc[2*ks][1]),
                h2pack(cc[2*ks][2],   cc[2*ks][3]),
                h2pack(cc[2*ks+1][0], cc[2*ks+1][1]),
                h2pack(cc[2*ks+1][2], cc[2*ks+1][3])
            };
            const int kb = ks * 8 + 2 * t;
#pragma unroll
            for (int nt = 0; nt < 8; nt++) {
                const uint2 vv = *(const uint2*)&Vb[(nt * 8 + g) * KW + kb];
                uint32_t bb[2] = { vv.x, vv.y };
                mma_f16(oacc[nt], a, bb);
            }
        }
        __syncthreads();
    }

    // epilogue: merged attn [B,S,H*64]
#pragma unroll
    for (int nt = 0; nt < 8; nt++) {
        const int d = h * 64 + nt * 8 + 2 * t;
        *(float2*)&g_attn[(size_t)(b_ * SSEQ + row0) * DM + d] =
            make_float2(oacc[nt][0], oacc[nt][1]);
        *(float2*)&g_attn[(size_t)(b_ * SSEQ + row0 + 8) * DM + d] =
            make_float2(oacc[nt][2], oacc[nt][3]);
    }
}

// ---------------------------------------------------------------------------
extern "C" void kernel_launch(void* const* d_in, const int* in_sizes, int n_in,
                              void* d_out, int out_size)
{
    const float* Q   = (const float*)d_in[0];
    const float* K   = (const float*)d_in[1];
    const float* V   = (const float*)d_in[2];
    const unsigned char* mask = (const unsigned char*)d_in[3];
    const float* WQw = (const float*)d_in[4];
    const float* WQb = (const float*)d_in[5];
    const float* WKw = (const float*)d_in[6];
    const float* WKb = (const float*)d_in[7];
    const float* WVw = (const float*)d_in[8];
    const float* WVb = (const float*)d_in[9];
    const float* Wow = (const float*)d_in[10];
    const float* Wob = (const float*)d_in[11];

    float* out   = (float*)d_out;                       // [B,S,D]
    float* attnw = out + (size_t)MTOT * DM;             // [B,H,S,S]

    void *pq, *pk, *pv, *pa;
    cudaGetSymbolAddress(&pq, g_q);
    cudaGetSymbolAddress(&pk, g_k);
    cudaGetSymbolAddress(&pv, g_vT);
    cudaGetSymbolAddress(&pa, g_attn);

    maskbits_kernel<<<(BB * SSEQ * (SSEQ / 32)) / 256, 256>>>(mask);

    proj_f16<<<dim3(8, 32), 256>>>(Q, WQw, WQb, pq, 1);
    proj_f16<<<dim3(8, 32), 256>>>(K, WKw, WKb, pk, 1);
    proj_f16<<<dim3(8, 32), 256>>>(V, WVw, WVb, pv, 2);

    fused_attn<<<dim3(16, 32), 256>>>(attnw);

    proj_f16<<<dim3(8, 32), 256>>>((const float*)pa, Wow, Wob, out, 0);
}

// round 9
// speedup vs baseline: 1.7026x; 1.1353x over previous
#include <cuda_runtime.h>
#include <cuda_fp16.h>
#include <cstdint>
#include <cstddef>

#define DM 1024
#define NH 16
#define DK 64
#define BB 2
#define SSEQ 2048
#define MTOT (BB*SSEQ)     // 4096
#define BH (BB*NH)         // 32

// Scratch (__device__ globals).  All half2-packed words (uint32).
// g_q/g_k: [bh][s][32 words], d half2-words sigma-permuted per 8-word group.
// g_vT:    [bh][64 d][1024 words], key half2-words sigma-permuted per 8-word group.
__device__ uint32_t g_q[(size_t)BH*SSEQ*32];
__device__ uint32_t g_k[(size_t)BH*SSEQ*32];
__device__ uint32_t g_vT[(size_t)BH*DK*1024];
__device__ float    g_attn[(size_t)MTOT*DM];
__device__ uint32_t g_mbits[(size_t)BB*SSEQ*(SSEQ/32)];

// ---------------------------------------------------------------------------
__device__ __forceinline__ uint32_t h2pack(float a, float b) {
    __half2 h = __floats2half2_rn(a, b);
    return *(uint32_t*)&h;
}
__device__ __forceinline__ void mma_f16(float* c, const uint32_t* a, const uint32_t* b) {
    asm volatile(
        "mma.sync.aligned.m16n8k16.row.col.f32.f16.f16.f32 "
        "{%0,%1,%2,%3}, {%4,%5,%6,%7}, {%8,%9}, {%0,%1,%2,%3};\n"
        : "+f"(c[0]), "+f"(c[1]), "+f"(c[2]), "+f"(c[3])
        : "r"(a[0]), "r"(a[1]), "r"(a[2]), "r"(a[3]), "r"(b[0]), "r"(b[1]));
}
__device__ __forceinline__ void cp16(uint32_t d, const void* s) {
    asm volatile("cp.async.ca.shared.global [%0], [%1], 16;\n" :: "r"(d), "l"(s));
}
__device__ __forceinline__ void cp_commit() { asm volatile("cp.async.commit_group;\n"); }
template<int N> __device__ __forceinline__ void cp_wait() {
    asm volatile("cp.async.wait_group %0;\n" :: "n"(N));
}
__device__ __host__ __forceinline__ int sigma8(int j) {
    return (j < 4) ? 2 * j : 2 * (j - 4) + 1;
}

// ---------------------------------------------------------------------------
__global__ void maskbits_kernel(const unsigned char* __restrict__ mask)
{
    const int idx = blockIdx.x * 256 + threadIdx.x;
    const uint32_t* src = (const uint32_t*)(mask + (size_t)idx * 32);
    uint32_t w = 0;
#pragma unroll
    for (int q = 0; q < 8; q++) {
        const uint32_t v = src[q];
        if (v & 0x000000ffu) w |= 1u << (q * 4 + 0);
        if (v & 0x0000ff00u) w |= 1u << (q * 4 + 1);
        if (v & 0x00ff0000u) w |= 1u << (q * 4 + 2);
        if (v & 0xff000000u) w |= 1u << (q * 4 + 3);
    }
    g_mbits[idx] = w;
}

// ---------------------------------------------------------------------------
// Projection GEMM, fp16 m16n8k16.  BK=32.  Stride 20 words (16 data + 4 pad),
// sigma-paired (w_j, w_{j+4}) adjacent -> frag = 1 LDS.64, conflict-free.
// Staging registers are packed half2 (8 regs/matrix) to fit 128-reg budget.
// mode 0: fp32 out[m][n]; mode 1: g_q/g_k layout; mode 2: g_vT layout
// ---------------------------------------------------------------------------
#define PW 20

__global__ void __launch_bounds__(256, 2) proj_f16(
    const float* __restrict__ A, const float* __restrict__ W,
    const float* __restrict__ bias, void* __restrict__ outv, int mode)
{
    __shared__ uint32_t As[128 * PW];
    __shared__ uint32_t Bs[128 * PW];
    const int tid = threadIdx.x;
    const int m0 = blockIdx.y * 128, n0 = blockIdx.x * 128;
    const int lane = tid & 31, warp = tid >> 5;
    const int wm = (warp & 3) * 32, wn = (warp >> 2) * 64;
    const int g = lane >> 2, t = lane & 3;
    const int row = tid >> 1;            // 0..127
    const int e = tid & 1;               // which k16 tile of BK32

    const float* Ab = A + (size_t)(m0 + row) * 1024 + e * 16;
    const float* Wb = W + (size_t)(n0 + row) * 1024 + e * 16;

    uint32_t pa[8], pw[8];
#pragma unroll
    for (int i = 0; i < 4; i++) {
        const float4 va = *(const float4*)(Ab + i * 4);
        const float4 vw = *(const float4*)(Wb + i * 4);
        pa[2*i]   = h2pack(va.x, va.y);
        pa[2*i+1] = h2pack(va.z, va.w);
        pw[2*i]   = h2pack(vw.x, vw.y);
        pw[2*i+1] = h2pack(vw.z, vw.w);
    }

    float c[2][8][4] = {};

    for (int k0 = 32; k0 <= 1024; k0 += 32) {
        {
            uint32_t* da = &As[row * PW + e * 8];
            uint32_t* dw = &Bs[row * PW + e * 8];
#pragma unroll
            for (int j = 0; j < 4; j++) {
                *(uint2*)&da[2*j] = make_uint2(pa[j], pa[j+4]);
                *(uint2*)&dw[2*j] = make_uint2(pw[j], pw[j+4]);
            }
        }
        __syncthreads();
        if (k0 < 1024) {
#pragma unroll
            for (int i = 0; i < 4; i++) {
                const float4 va = *(const float4*)(Ab + k0 + i * 4);
                const float4 vw = *(const float4*)(Wb + k0 + i * 4);
                pa[2*i]   = h2pack(va.x, va.y);
                pa[2*i+1] = h2pack(va.z, va.w);
                pw[2*i]   = h2pack(vw.x, vw.y);
                pw[2*i+1] = h2pack(vw.z, vw.w);
            }
        }
#pragma unroll
        for (int ks = 0; ks < 2; ks++) {
            const int kb = ks * 8 + 2 * t;
            uint32_t af[2][4], bf[8][2];
#pragma unroll
            for (int mi = 0; mi < 2; mi++) {
                const int r = wm + mi * 16 + g;
                const uint2 x = *(const uint2*)&As[r * PW + kb];
                const uint2 y = *(const uint2*)&As[(r + 8) * PW + kb];
                af[mi][0] = x.x; af[mi][2] = x.y;
                af[mi][1] = y.x; af[mi][3] = y.y;
            }
#pragma unroll
            for (int ni = 0; ni < 8; ni++) {
                const uint2 z = *(const uint2*)&Bs[(wn + ni * 8 + g) * PW + kb];
                bf[ni][0] = z.x; bf[ni][1] = z.y;
            }
#pragma unroll
            for (int mi = 0; mi < 2; mi++)
#pragma unroll
                for (int ni = 0; ni < 8; ni++)
                    mma_f16(c[mi][ni], af[mi], bf[ni]);
        }
        __syncthreads();
    }

#pragma unroll
    for (int mi = 0; mi < 2; mi++) {
#pragma unroll
        for (int rr = 0; rr < 2; rr++) {
            const int m = m0 + wm + mi * 16 + g + rr * 8;
            const int b_ = m >> 11, s = m & 2047;
#pragma unroll
            for (int ni = 0; ni < 8; ni++) {
                const int n = n0 + wn + ni * 8 + 2 * t;
                const float v0 = c[mi][ni][rr * 2 + 0] + bias[n];
                const float v1 = c[mi][ni][rr * 2 + 1] + bias[n + 1];
                if (mode == 0) {
                    *(float2*)&((float*)outv)[(size_t)m * 1024 + n] = make_float2(v0, v1);
                } else if (mode == 1) {
                    // g_q/g_k: [bh][s][32 words]
                    const int h = n >> 6;
                    const int ni_l = (n & 63) >> 3;
                    const int widx = (ni_l >> 1) * 8 + 2 * t + (ni_l & 1);
                    ((uint32_t*)outv)[((size_t)(b_ * 16 + h) * 2048 + s) * 32 + widx] =
                        h2pack(v0, v1);
                } else {
                    // g_vT half view: [bh][64 d][2048 keys], key words sigma'd
                    const int h = n >> 6;
                    const int dn = n & 63;
                    const int sw = (s >> 4) * 16 + sigma8((s & 15) >> 1) * 2 + (s & 1);
                    __half* vh = (__half*)outv;
                    vh[((size_t)(b_ * 16 + h) * 64 + dn) * 2048 + sw]     = __float2half_rn(v0);
                    vh[((size_t)(b_ * 16 + h) * 64 + dn + 1) * 2048 + sw] = __float2half_rn(v1);
                }
            }
        }
    }
}

// ---------------------------------------------------------------------------
// Fused attention, fp16 (unchanged from R8).
// ---------------------------------------------------------------------------
#define CK 64
#define NCH (SSEQ/CK)         // 32
#define KW 40                 // words per smem row
#define KBUF (CK*KW)          // 2560 words

__global__ void __launch_bounds__(256, 2) fused_attn(float* __restrict__ P)
{
    __shared__ uint32_t sm[4 * KBUF];    // K0 K1 V0 V1 = 40 KB
    const int tid = threadIdx.x;
    const int lane = tid & 31, warp = tid >> 5;
    const int g = lane >> 2, t = lane & 3;
    const int bh = blockIdx.y;
    const int i0 = blockIdx.x * 128;
    const int b_ = bh >> 4, h = bh & 15;
    const int wm = warp * 16;
    const int row0 = i0 + wm + g;

    const uint32_t* Kg = g_k + (size_t)bh * SSEQ * 32;
    const uint32_t* Vg = g_vT + (size_t)bh * DK * 1024;
    float* Pg = P + (size_t)bh * SSEQ * SSEQ;
    const uint32_t* mb0 = g_mbits + ((size_t)b_ * SSEQ + row0) * 64;
    const uint32_t* mb1 = mb0 + (size_t)8 * 64;

    const uint32_t sbase = (uint32_t)__cvta_generic_to_shared(sm);

    auto stageK = [&](int c) {
        const uint32_t dbase = sbase + ((c & 1) ? KBUF : 0) * 4;
        const uint32_t* src = Kg + (size_t)c * CK * 32;
#pragma unroll
        for (int s = 0; s < 2; s++) {
            const int idx = tid + s * 256;
            const int key = idx >> 3, seg = idx & 7;
            cp16(dbase + (uint32_t)(key * KW + seg * 4) * 4, src + key * 32 + seg * 4);
        }
    };
    auto stageV = [&](int c) {
        const uint32_t dbase = sbase + ((c & 1) ? 3 * KBUF : 2 * KBUF) * 4;
#pragma unroll
        for (int s = 0; s < 2; s++) {
            const int idx = tid + s * 256;
            const int d = idx >> 3, seg = idx & 7;
            cp16(dbase + (uint32_t)(d * KW + seg * 4) * 4,
                 Vg + (size_t)d * 1024 + c * 32 + seg * 4);
        }
    };

    // Q fragments -> registers, once
    uint32_t qf[4][4];
#pragma unroll
    for (int ks = 0; ks < 4; ks++) {
        const uint2 qa = *(const uint2*)&g_q[((size_t)bh * SSEQ + row0) * 32 + ks * 8 + 2 * t];
        const uint2 qb = *(const uint2*)&g_q[((size_t)bh * SSEQ + row0 + 8) * 32 + ks * 8 + 2 * t];
        qf[ks][0] = qa.x; qf[ks][2] = qa.y;
        qf[ks][1] = qb.x; qf[ks][3] = qb.y;
    }

    auto qk = [&](const uint32_t* Kb, float cc[8][4]) {
#pragma unroll
        for (int ks = 0; ks < 4; ks++) {
            const int kb = ks * 8 + 2 * t;
#pragma unroll
            for (int nt = 0; nt < 8; nt++) {
                const uint2 kv = *(const uint2*)&Kb[(nt * 8 + g) * KW + kb];
                uint32_t bb[2] = { kv.x, kv.y };
                mma_f16(cc[nt], qf[ks], bb);
            }
        }
    };

    // ================= PASS A: row sums =================
    float l0 = 0.f, l1 = 0.f;
    stageK(0); cp_commit();
    for (int c = 0; c < NCH; c++) {
        if (c + 1 < NCH) { stageK(c + 1); cp_commit(); cp_wait<1>(); }
        else             { cp_wait<0>(); }
        __syncthreads();
        const uint32_t* Kb = sm + ((c & 1) ? KBUF : 0);
        float cc[8][4] = {};
        qk(Kb, cc);
        const uint2 w0 = *(const uint2*)(mb0 + c * 2);
        const uint2 w1 = *(const uint2*)(mb1 + c * 2);
#pragma unroll
        for (int nt = 0; nt < 8; nt++) {
            const int sh = (nt * 8) & 31;
            const uint32_t m0w = (nt < 4) ? w0.x : w0.y;
            const uint32_t m1w = (nt < 4) ? w1.x : w1.y;
            l0 += ((m0w >> (sh + 2 * t))     & 1) ? 0.f : __expf(cc[nt][0] * 0.125f);
            l0 += ((m0w >> (sh + 2 * t + 1)) & 1) ? 0.f : __expf(cc[nt][1] * 0.125f);
            l1 += ((m1w >> (sh + 2 * t))     & 1) ? 0.f : __expf(cc[nt][2] * 0.125f);
            l1 += ((m1w >> (sh + 2 * t + 1)) & 1) ? 0.f : __expf(cc[nt][3] * 0.125f);
        }
        __syncthreads();
    }
    l0 += __shfl_xor_sync(0xffffffffu, l0, 1);
    l0 += __shfl_xor_sync(0xffffffffu, l0, 2);
    l1 += __shfl_xor_sync(0xffffffffu, l1, 1);
    l1 += __shfl_xor_sync(0xffffffffu, l1, 2);
    const float inv0 = 1.f / l0, inv1 = 1.f / l1;

    // ================= PASS B: normalize + write P + PV =================
    float oacc[8][4] = {};
    stageK(0); stageV(0); cp_commit();
    for (int c = 0; c < NCH; c++) {
        if (c + 1 < NCH) { stageK(c + 1); stageV(c + 1); cp_commit(); cp_wait<1>(); }
        else             { cp_wait<0>(); }
        __syncthreads();
        const uint32_t* Kb = sm + ((c & 1) ? KBUF : 0);
        const uint32_t* Vb = sm + ((c & 1) ? 3 * KBUF : 2 * KBUF);
        float cc[8][4] = {};
        qk(Kb, cc);
        const int jc = c * CK;
        const uint2 w0 = *(const uint2*)(mb0 + c * 2);
        const uint2 w1 = *(const uint2*)(mb1 + c * 2);
#pragma unroll
        for (int nt = 0; nt < 8; nt++) {
            const int sh = (nt * 8) & 31;
            const uint32_t m0w = (nt < 4) ? w0.x : w0.y;
            const uint32_t m1w = (nt < 4) ? w1.x : w1.y;
            cc[nt][0] = ((m0w >> (sh + 2 * t))     & 1) ? 0.f : __expf(cc[nt][0] * 0.125f) * inv0;
            cc[nt][1] = ((m0w >> (sh + 2 * t + 1)) & 1) ? 0.f : __expf(cc[nt][1] * 0.125f) * inv0;
            cc[nt][2] = ((m1w >> (sh + 2 * t))     & 1) ? 0.f : __expf(cc[nt][2] * 0.125f) * inv1;
            cc[nt][3] = ((m1w >> (sh + 2 * t + 1)) & 1) ? 0.f : __expf(cc[nt][3] * 0.125f) * inv1;
            *(float2*)&Pg[(size_t)row0 * SSEQ + jc + nt * 8 + 2 * t] =
                make_float2(cc[nt][0], cc[nt][1]);
            *(float2*)&Pg[(size_t)(row0 + 8) * SSEQ + jc + nt * 8 + 2 * t] =
                make_float2(cc[nt][2], cc[nt][3]);
        }
        // PV: a-frags packed straight from c-frags (natural layout)
#pragma unroll
        for (int ks = 0; ks < 4; ks++) {
            uint32_t a[4] = {
                h2pack(cc[2*ks][0],   cc[2*ks][1]),
                h2pack(cc[2*ks][2],   cc[2*ks][3]),
                h2pack(cc[2*ks+1][0], cc[2*ks+1][1]),
                h2pack(cc[2*ks+1][2], cc[2*ks+1][3])
            };
            const int kb = ks * 8 + 2 * t;
#pragma unroll
            for (int nt = 0; nt < 8; nt++) {
                const uint2 vv = *(const uint2*)&Vb[(nt * 8 + g) * KW + kb];
                uint32_t bb[2] = { vv.x, vv.y };
                mma_f16(oacc[nt], a, bb);
            }
        }
        __syncthreads();
    }

    // epilogue: merged attn [B,S,H*64]
#pragma unroll
    for (int nt = 0; nt < 8; nt++) {
        const int d = h * 64 + nt * 8 + 2 * t;
        *(float2*)&g_attn[(size_t)(b_ * SSEQ + row0) * DM + d] =
            make_float2(oacc[nt][0], oacc[nt][1]);
        *(float2*)&g_attn[(size_t)(b_ * SSEQ + row0 + 8) * DM + d] =
            make_float2(oacc[nt][2], oacc[nt][3]);
    }
}

// ---------------------------------------------------------------------------
extern "C" void kernel_launch(void* const* d_in, const int* in_sizes, int n_in,
                              void* d_out, int out_size)
{
    const float* Q   = (const float*)d_in[0];
    const float* K   = (const float*)d_in[1];
    const float* V   = (const float*)d_in[2];
    const unsigned char* mask = (const unsigned char*)d_in[3];
    const float* WQw = (const float*)d_in[4];
    const float* WQb = (const float*)d_in[5];
    const float* WKw = (const float*)d_in[6];
    const float* WKb = (const float*)d_in[7];
    const float* WVw = (const float*)d_in[8];
    const float* WVb = (const float*)d_in[9];
    const float* Wow = (const float*)d_in[10];
    const float* Wob = (const float*)d_in[11];

    float* out   = (float*)d_out;                       // [B,S,D]
    float* attnw = out + (size_t)MTOT * DM;             // [B,H,S,S]

    void *pq, *pk, *pv, *pa;
    cudaGetSymbolAddress(&pq, g_q);
    cudaGetSymbolAddress(&pk, g_k);
    cudaGetSymbolAddress(&pv, g_vT);
    cudaGetSymbolAddress(&pa, g_attn);

    maskbits_kernel<<<(BB * SSEQ * (SSEQ / 32)) / 256, 256>>>(mask);

    proj_f16<<<dim3(8, 32), 256>>>(Q, WQw, WQb, pq, 1);
    proj_f16<<<dim3(8, 32), 256>>>(K, WKw, WKb, pk, 1);
    proj_f16<<<dim3(8, 32), 256>>>(V, WVw, WVb, pv, 2);

    fused_attn<<<dim3(16, 32), 256>>>(attnw);

    proj_f16<<<dim3(8, 32), 256>>>((const float*)pa, Wow, Wob, out, 0);
}

// round 10
// speedup vs baseline: 1.9167x; 1.1258x over previous
#include <cuda_runtime.h>
#include <cuda_fp16.h>
#include <cstdint>
#include <cstddef>

#define DM 1024
#define NH 16
#define DK 64
#define BB 2
#define SSEQ 2048
#define MTOT (BB*SSEQ)     // 4096
#define BH (BB*NH)         // 32

// Packed half2 words (uint32), k/d sigma-paired within 8-word (16-half) groups.
__device__ uint32_t g_Qh[(size_t)MTOT*512];    // packed Q input
__device__ uint32_t g_Kh[(size_t)MTOT*512];
__device__ uint32_t g_Vh[(size_t)MTOT*512];
__device__ uint32_t g_Wh[4][(size_t)DM*512];   // packed WQ,WK,WV,Wo
__device__ uint32_t g_q[(size_t)BH*SSEQ*32];   // projected q [bh][s][32w]
__device__ uint32_t g_k[(size_t)BH*SSEQ*32];
__device__ uint32_t g_vT[(size_t)BH*DK*1024];  // [bh][64 d][1024w keys sigma'd]
__device__ uint32_t g_attnh[(size_t)MTOT*512]; // merged attn, packed
__device__ uint32_t g_mbits[(size_t)BB*SSEQ*(SSEQ/32)];

// ---------------------------------------------------------------------------
__device__ __forceinline__ uint32_t h2pack(float a, float b) {
    __half2 h = __floats2half2_rn(a, b);
    return *(uint32_t*)&h;
}
__device__ __forceinline__ void mma_f16(float* c, const uint32_t* a, const uint32_t* b) {
    asm volatile(
        "mma.sync.aligned.m16n8k16.row.col.f32.f16.f16.f32 "
        "{%0,%1,%2,%3}, {%4,%5,%6,%7}, {%8,%9}, {%0,%1,%2,%3};\n"
        : "+f"(c[0]), "+f"(c[1]), "+f"(c[2]), "+f"(c[3])
        : "r"(a[0]), "r"(a[1]), "r"(a[2]), "r"(a[3]), "r"(b[0]), "r"(b[1]));
}
__device__ __forceinline__ void cp16(uint32_t d, const void* s) {
    asm volatile("cp.async.ca.shared.global [%0], [%1], 16;\n" :: "r"(d), "l"(s));
}
__device__ __forceinline__ void cp_commit() { asm volatile("cp.async.commit_group;\n"); }
template<int N> __device__ __forceinline__ void cp_wait() {
    asm volatile("cp.async.wait_group %0;\n" :: "n"(N));
}
__device__ __host__ __forceinline__ int sigma8(int j) {
    return (j < 4) ? 2 * j : 2 * (j - 4) + 1;
}

// ---------------------------------------------------------------------------
__global__ void maskbits_kernel(const unsigned char* __restrict__ mask)
{
    const int idx = blockIdx.x * 256 + threadIdx.x;
    const uint32_t* src = (const uint32_t*)(mask + (size_t)idx * 32);
    uint32_t w = 0;
#pragma unroll
    for (int q = 0; q < 8; q++) {
        const uint32_t v = src[q];
        if (v & 0x000000ffu) w |= 1u << (q * 4 + 0);
        if (v & 0x0000ff00u) w |= 1u << (q * 4 + 1);
        if (v & 0x00ff0000u) w |= 1u << (q * 4 + 2);
        if (v & 0xff000000u) w |= 1u << (q * 4 + 3);
    }
    g_mbits[idx] = w;
}

// ---------------------------------------------------------------------------
// fp32 -> sigma-packed half2 words.  One thread = one 16-value group.
// out words: [w0 w4 w1 w5 w2 w6 w3 w7]  (phys(j) = j<4 ? 2j : 2j-7)
// ---------------------------------------------------------------------------
__global__ void pack_sigma(const float* __restrict__ src, uint32_t* __restrict__ dst)
{
    const int idx = blockIdx.x * 256 + threadIdx.x;
    const float* s = src + (size_t)idx * 16;
    uint32_t w[8];
#pragma unroll
    for (int j = 0; j < 8; j++) {
        const float2 v = *(const float2*)(s + 2 * j);
        w[j] = h2pack(v.x, v.y);
    }
    uint4* d = (uint4*)(dst + (size_t)idx * 8);
    d[0] = make_uint4(w[0], w[4], w[1], w[5]);
    d[1] = make_uint4(w[2], w[6], w[3], w[7]);
}

// ---------------------------------------------------------------------------
// Projection GEMM v3: pure-half operands, cp.async double-buffered.
// A: [M][512w] packed; W: [1024][512w] packed.  BK=32 halfs = 16 words/row.
// Smem row stride PW=20 words; frag = LDS.64, conflict-free.
// mode 0: fp32 out[m][n]; mode 1: g_q/g_k layout; mode 2: g_vT layout
// ---------------------------------------------------------------------------
#define PW 20
#define TILE_W (128*PW)      // words per matrix buffer

__global__ void __launch_bounds__(256, 2) proj_f16(
    const uint32_t* __restrict__ Ah, const uint32_t* __restrict__ Wh,
    const float* __restrict__ bias, void* __restrict__ outv, int mode)
{
    __shared__ uint32_t sm[4 * TILE_W];   // A0 B0 A1 B1 = 40 KB
    const int tid = threadIdx.x;
    const int m0 = blockIdx.y * 128, n0 = blockIdx.x * 128;
    const int lane = tid & 31, warp = tid >> 5;
    const int wm = (warp & 3) * 32, wn = (warp >> 2) * 64;
    const int g = lane >> 2, t = lane & 3;
    const int row = tid >> 1;            // 0..127
    const int e = tid & 1;               // half-row (8 words)

    const uint32_t sbase = (uint32_t)__cvta_generic_to_shared(sm);
    const uint32_t* As_src = Ah + (size_t)(m0 + row) * 512 + e * 8;
    const uint32_t* Ws_src = Wh + (size_t)(n0 + row) * 512 + e * 8;
    const uint32_t dA = sbase + (uint32_t)(row * PW + e * 8) * 4;
    const uint32_t dB = dA + TILE_W * 4;

    auto stage = [&](int tile, int buf) {
        const uint32_t off = (uint32_t)(buf * 2 * TILE_W) * 4;
        const uint32_t* a = As_src + tile * 16;
        const uint32_t* w = Ws_src + tile * 16;
        cp16(dA + off, a);
        cp16(dA + off + 16, a + 4);
        cp16(dB + off, w);
        cp16(dB + off + 16, w + 4);
    };

    float c[2][8][4] = {};

    stage(0, 0); cp_commit();
    for (int tl = 0; tl < 32; tl++) {
        if (tl + 1 < 32) { stage(tl + 1, (tl + 1) & 1); cp_commit(); cp_wait<1>(); }
        else             { cp_wait<0>(); }
        __syncthreads();
        const uint32_t* As = sm + (tl & 1) * 2 * TILE_W;
        const uint32_t* Bs = As + TILE_W;
#pragma unroll
        for (int ks = 0; ks < 2; ks++) {
            const int kb = ks * 8 + 2 * t;
            uint32_t af[2][4], bf[8][2];
#pragma unroll
            for (int mi = 0; mi < 2; mi++) {
                const int r = wm + mi * 16 + g;
                const uint2 x = *(const uint2*)&As[r * PW + kb];
                const uint2 y = *(const uint2*)&As[(r + 8) * PW + kb];
                af[mi][0] = x.x; af[mi][2] = x.y;
                af[mi][1] = y.x; af[mi][3] = y.y;
            }
#pragma unroll
            for (int ni = 0; ni < 8; ni++) {
                const uint2 z = *(const uint2*)&Bs[(wn + ni * 8 + g) * PW + kb];
                bf[ni][0] = z.x; bf[ni][1] = z.y;
            }
#pragma unroll
            for (int mi = 0; mi < 2; mi++)
#pragma unroll
                for (int ni = 0; ni < 8; ni++)
                    mma_f16(c[mi][ni], af[mi], bf[ni]);
        }
        __syncthreads();
    }

#pragma unroll
    for (int mi = 0; mi < 2; mi++) {
#pragma unroll
        for (int rr = 0; rr < 2; rr++) {
            const int m = m0 + wm + mi * 16 + g + rr * 8;
            const int b_ = m >> 11, s = m & 2047;
#pragma unroll
            for (int ni = 0; ni < 8; ni++) {
                const int n = n0 + wn + ni * 8 + 2 * t;
                const float v0 = c[mi][ni][rr * 2 + 0] + bias[n];
                const float v1 = c[mi][ni][rr * 2 + 1] + bias[n + 1];
                if (mode == 0) {
                    *(float2*)&((float*)outv)[(size_t)m * 1024 + n] = make_float2(v0, v1);
                } else if (mode == 1) {
                    const int h = n >> 6;
                    const int ni_l = (n & 63) >> 3;
                    const int widx = (ni_l >> 1) * 8 + 2 * t + (ni_l & 1);
                    ((uint32_t*)outv)[((size_t)(b_ * 16 + h) * 2048 + s) * 32 + widx] =
                        h2pack(v0, v1);
                } else {
                    const int h = n >> 6;
                    const int dn = n & 63;
                    const int sw = (s >> 4) * 16 + sigma8((s & 15) >> 1) * 2 + (s & 1);
                    __half* vh = (__half*)outv;
                    vh[((size_t)(b_ * 16 + h) * 64 + dn) * 2048 + sw]     = __float2half_rn(v0);
                    vh[((size_t)(b_ * 16 + h) * 64 + dn + 1) * 2048 + sw] = __float2half_rn(v1);
                }
            }
        }
    }
}

// ---------------------------------------------------------------------------
// Fused attention, fp16 (R8 structure; epilogue writes packed g_attnh).
// ---------------------------------------------------------------------------
#define CK 64
#define NCH (SSEQ/CK)         // 32
#define KW 40
#define KBUF (CK*KW)          // 2560 words

__global__ void __launch_bounds__(256, 2) fused_attn(float* __restrict__ P)
{
    __shared__ uint32_t sm[4 * KBUF];    // K0 K1 V0 V1 = 40 KB
    const int tid = threadIdx.x;
    const int lane = tid & 31, warp = tid >> 5;
    const int g = lane >> 2, t = lane & 3;
    const int bh = blockIdx.y;
    const int i0 = blockIdx.x * 128;
    const int b_ = bh >> 4, h = bh & 15;
    const int wm = warp * 16;
    const int row0 = i0 + wm + g;

    const uint32_t* Kg = g_k + (size_t)bh * SSEQ * 32;
    const uint32_t* Vg = g_vT + (size_t)bh * DK * 1024;
    float* Pg = P + (size_t)bh * SSEQ * SSEQ;
    const uint32_t* mb0 = g_mbits + ((size_t)b_ * SSEQ + row0) * 64;
    const uint32_t* mb1 = mb0 + (size_t)8 * 64;

    const uint32_t sbase = (uint32_t)__cvta_generic_to_shared(sm);

    auto stageK = [&](int c) {
        const uint32_t dbase = sbase + ((c & 1) ? KBUF : 0) * 4;
        const uint32_t* src = Kg + (size_t)c * CK * 32;
#pragma unroll
        for (int s = 0; s < 2; s++) {
            const int idx = tid + s * 256;
            const int key = idx >> 3, seg = idx & 7;
            cp16(dbase + (uint32_t)(key * KW + seg * 4) * 4, src + key * 32 + seg * 4);
        }
    };
    auto stageV = [&](int c) {
        const uint32_t dbase = sbase + ((c & 1) ? 3 * KBUF : 2 * KBUF) * 4;
#pragma unroll
        for (int s = 0; s < 2; s++) {
            const int idx = tid + s * 256;
            const int d = idx >> 3, seg = idx & 7;
            cp16(dbase + (uint32_t)(d * KW + seg * 4) * 4,
                 Vg + (size_t)d * 1024 + c * 32 + seg * 4);
        }
    };

    uint32_t qf[4][4];
#pragma unroll
    for (int ks = 0; ks < 4; ks++) {
        const uint2 qa = *(const uint2*)&g_q[((size_t)bh * SSEQ + row0) * 32 + ks * 8 + 2 * t];
        const uint2 qb = *(const uint2*)&g_q[((size_t)bh * SSEQ + row0 + 8) * 32 + ks * 8 + 2 * t];
        qf[ks][0] = qa.x; qf[ks][2] = qa.y;
        qf[ks][1] = qb.x; qf[ks][3] = qb.y;
    }

    auto qk = [&](const uint32_t* Kb, float cc[8][4]) {
#pragma unroll
        for (int ks = 0; ks < 4; ks++) {
            const int kb = ks * 8 + 2 * t;
#pragma unroll
            for (int nt = 0; nt < 8; nt++) {
                const uint2 kv = *(const uint2*)&Kb[(nt * 8 + g) * KW + kb];
                uint32_t bb[2] = { kv.x, kv.y };
                mma_f16(cc[nt], qf[ks], bb);
            }
        }
    };

    // ================= PASS A =================
    float l0 = 0.f, l1 = 0.f;
    stageK(0); cp_commit();
    for (int c = 0; c < NCH; c++) {
        if (c + 1 < NCH) { stageK(c + 1); cp_commit(); cp_wait<1>(); }
        else             { cp_wait<0>(); }
        __syncthreads();
        const uint32_t* Kb = sm + ((c & 1) ? KBUF : 0);
        float cc[8][4] = {};
        qk(Kb, cc);
        const uint2 w0 = *(const uint2*)(mb0 + c * 2);
        const uint2 w1 = *(const uint2*)(mb1 + c * 2);
#pragma unroll
        for (int nt = 0; nt < 8; nt++) {
            const int sh = (nt * 8) & 31;
            const uint32_t m0w = (nt < 4) ? w0.x : w0.y;
            const uint32_t m1w = (nt < 4) ? w1.x : w1.y;
            l0 += ((m0w >> (sh + 2 * t))     & 1) ? 0.f : __expf(cc[nt][0] * 0.125f);
            l0 += ((m0w >> (sh + 2 * t + 1)) & 1) ? 0.f : __expf(cc[nt][1] * 0.125f);
            l1 += ((m1w >> (sh + 2 * t))     & 1) ? 0.f : __expf(cc[nt][2] * 0.125f);
            l1 += ((m1w >> (sh + 2 * t + 1)) & 1) ? 0.f : __expf(cc[nt][3] * 0.125f);
        }
        __syncthreads();
    }
    l0 += __shfl_xor_sync(0xffffffffu, l0, 1);
    l0 += __shfl_xor_sync(0xffffffffu, l0, 2);
    l1 += __shfl_xor_sync(0xffffffffu, l1, 1);
    l1 += __shfl_xor_sync(0xffffffffu, l1, 2);
    const float inv0 = 1.f / l0, inv1 = 1.f / l1;

    // ================= PASS B =================
    float oacc[8][4] = {};
    stageK(0); stageV(0); cp_commit();
    for (int c = 0; c < NCH; c++) {
        if (c + 1 < NCH) { stageK(c + 1); stageV(c + 1); cp_commit(); cp_wait<1>(); }
        else             { cp_wait<0>(); }
        __syncthreads();
        const uint32_t* Kb = sm + ((c & 1) ? KBUF : 0);
        const uint32_t* Vb = sm + ((c & 1) ? 3 * KBUF : 2 * KBUF);
        float cc[8][4] = {};
        qk(Kb, cc);
        const int jc = c * CK;
        const uint2 w0 = *(const uint2*)(mb0 + c * 2);
        const uint2 w1 = *(const uint2*)(mb1 + c * 2);
#pragma unroll
        for (int nt = 0; nt < 8; nt++) {
            const int sh = (nt * 8) & 31;
            const uint32_t m0w = (nt < 4) ? w0.x : w0.y;
            const uint32_t m1w = (nt < 4) ? w1.x : w1.y;
            cc[nt][0] = ((m0w >> (sh + 2 * t))     & 1) ? 0.f : __expf(cc[nt][0] * 0.125f) * inv0;
            cc[nt][1] = ((m0w >> (sh + 2 * t + 1)) & 1) ? 0.f : __expf(cc[nt][1] * 0.125f) * inv0;
            cc[nt][2] = ((m1w >> (sh + 2 * t))     & 1) ? 0.f : __expf(cc[nt][2] * 0.125f) * inv1;
            cc[nt][3] = ((m1w >> (sh + 2 * t + 1)) & 1) ? 0.f : __expf(cc[nt][3] * 0.125f) * inv1;
            *(float2*)&Pg[(size_t)row0 * SSEQ + jc + nt * 8 + 2 * t] =
                make_float2(cc[nt][0], cc[nt][1]);
            *(float2*)&Pg[(size_t)(row0 + 8) * SSEQ + jc + nt * 8 + 2 * t] =
                make_float2(cc[nt][2], cc[nt][3]);
        }
#pragma unroll
        for (int ks = 0; ks < 4; ks++) {
            uint32_t a[4] = {
                h2pack(cc[2*ks][0],   cc[2*ks][1]),
                h2pack(cc[2*ks][2],   cc[2*ks][3]),
                h2pack(cc[2*ks+1][0], cc[2*ks+1][1]),
                h2pack(cc[2*ks+1][2], cc[2*ks+1][3])
            };
            const int kb = ks * 8 + 2 * t;
#pragma unroll
            for (int nt = 0; nt < 8; nt++) {
                const uint2 vv = *(const uint2*)&Vb[(nt * 8 + g) * KW + kb];
                uint32_t bb[2] = { vv.x, vv.y };
                mma_f16(oacc[nt], a, bb);
            }
        }
        __syncthreads();
    }

    // epilogue: packed merged attn (same rounding the proj staging used to do)
#pragma unroll
    for (int nt = 0; nt < 8; nt++) {
        const int widx = (h * 4 + (nt >> 1)) * 8 + 2 * t + (nt & 1);
        g_attnh[((size_t)(b_ * SSEQ + row0)) * 512 + widx]     = h2pack(oacc[nt][0], oacc[nt][1]);
        g_attnh[((size_t)(b_ * SSEQ + row0 + 8)) * 512 + widx] = h2pack(oacc[nt][2], oacc[nt][3]);
    }
}

// ---------------------------------------------------------------------------
extern "C" void kernel_launch(void* const* d_in, const int* in_sizes, int n_in,
                              void* d_out, int out_size)
{
    const float* Q   = (const float*)d_in[0];
    const float* K   = (const float*)d_in[1];
    const float* V   = (const float*)d_in[2];
    const unsigned char* mask = (const unsigned char*)d_in[3];
    const float* WQw = (const float*)d_in[4];
    const float* WQb = (const float*)d_in[5];
    const float* WKw = (const float*)d_in[6];
    const float* WKb = (const float*)d_in[7];
    const float* WVw = (const float*)d_in[8];
    const float* WVb = (const float*)d_in[9];
    const float* Wow = (const float*)d_in[10];
    const float* Wob = (const float*)d_in[11];

    float* out   = (float*)d_out;                       // [B,S,D]
    float* attnw = out + (size_t)MTOT * DM;             // [B,H,S,S]

    void *pQh, *pKh, *pVh, *pWh, *pq, *pk, *pv, *pah;
    cudaGetSymbolAddress(&pQh, g_Qh);
    cudaGetSymbolAddress(&pKh, g_Kh);
    cudaGetSymbolAddress(&pVh, g_Vh);
    cudaGetSymbolAddress(&pWh, g_Wh);
    cudaGetSymbolAddress(&pq, g_q);
    cudaGetSymbolAddress(&pk, g_k);
    cudaGetSymbolAddress(&pv, g_vT);
    cudaGetSymbolAddress(&pah, g_attnh);

    uint32_t* Wh0 = (uint32_t*)pWh;

    maskbits_kernel<<<(BB * SSEQ * (SSEQ / 32)) / 256, 256>>>(mask);

    // prepass: pack activations + weights to sigma-paired half2
    pack_sigma<<<1024, 256>>>(Q, (uint32_t*)pQh);
    pack_sigma<<<1024, 256>>>(K, (uint32_t*)pKh);
    pack_sigma<<<1024, 256>>>(V, (uint32_t*)pVh);
    pack_sigma<<<256, 256>>>(WQw, Wh0 + 0 * (size_t)DM * 512);
    pack_sigma<<<256, 256>>>(WKw, Wh0 + 1 * (size_t)DM * 512);
    pack_sigma<<<256, 256>>>(WVw, Wh0 + 2 * (size_t)DM * 512);
    pack_sigma<<<256, 256>>>(Wow, Wh0 + 3 * (size_t)DM * 512);

    proj_f16<<<dim3(8, 32), 256>>>((const uint32_t*)pQh, Wh0 + 0 * (size_t)DM * 512, WQb, pq, 1);
    proj_f16<<<dim3(8, 32), 256>>>((const uint32_t*)pKh, Wh0 + 1 * (size_t)DM * 512, WKb, pk, 1);
    proj_f16<<<dim3(8, 32), 256>>>((const uint32_t*)pVh, Wh0 + 2 * (size_t)DM * 512, WVb, pv, 2);

    fused_attn<<<dim3(16, 32), 256>>>(attnw);

    proj_f16<<<dim3(8, 32), 256>>>((const uint32_t*)pah, Wh0 + 3 * (size_t)DM * 512, Wob, out, 0);
}

// round 11
// speedup vs baseline: 1.9935x; 1.0401x over previous
#include <cuda_runtime.h>
#include <cuda_fp16.h>
#include <cstdint>
#include <cstddef>

#define DM 1024
#define NH 16
#define DK 64
#define BB 2
#define SSEQ 2048
#define MTOT (BB*SSEQ)     // 4096
#define BH (BB*NH)         // 32

// Packed half2 words (uint32), k/d sigma-paired within 8-word (16-half) groups.
__device__ uint32_t g_Qh[(size_t)MTOT*512];
__device__ uint32_t g_Kh[(size_t)MTOT*512];
__device__ uint32_t g_Vh[(size_t)MTOT*512];
__device__ uint32_t g_Wh[4][(size_t)DM*512];
__device__ uint32_t g_q[(size_t)BH*SSEQ*32];   // projected q [bh][s][32w]
__device__ uint32_t g_k[(size_t)BH*SSEQ*32];
__device__ uint32_t g_vT[(size_t)BH*DK*1024];  // [bh][64 d][1024w keys sigma'd]
__device__ uint32_t g_attnh[(size_t)MTOT*512]; // merged attn, packed
__device__ uint32_t g_mbits[(size_t)BB*SSEQ*(SSEQ/32)];

// ---------------------------------------------------------------------------
__device__ __forceinline__ uint32_t h2pack(float a, float b) {
    __half2 h = __floats2half2_rn(a, b);
    return *(uint32_t*)&h;
}
__device__ __forceinline__ void mma_f16(float* c, const uint32_t* a, const uint32_t* b) {
    asm volatile(
        "mma.sync.aligned.m16n8k16.row.col.f32.f16.f16.f32 "
        "{%0,%1,%2,%3}, {%4,%5,%6,%7}, {%8,%9}, {%0,%1,%2,%3};\n"
        : "+f"(c[0]), "+f"(c[1]), "+f"(c[2]), "+f"(c[3])
        : "r"(a[0]), "r"(a[1]), "r"(a[2]), "r"(a[3]), "r"(b[0]), "r"(b[1]));
}
__device__ __forceinline__ void cp16(uint32_t d, const void* s) {
    asm volatile("cp.async.ca.shared.global [%0], [%1], 16;\n" :: "r"(d), "l"(s));
}
__device__ __forceinline__ void cp_commit() { asm volatile("cp.async.commit_group;\n"); }
template<int N> __device__ __forceinline__ void cp_wait() {
    asm volatile("cp.async.wait_group %0;\n" :: "n"(N));
}
__device__ __host__ __forceinline__ int sigma8(int j) {
    return (j < 4) ? 2 * j : 2 * (j - 4) + 1;
}

// ---------------------------------------------------------------------------
__global__ void maskbits_kernel(const unsigned char* __restrict__ mask)
{
    const int idx = blockIdx.x * 256 + threadIdx.x;
    const uint32_t* src = (const uint32_t*)(mask + (size_t)idx * 32);
    uint32_t w = 0;
#pragma unroll
    for (int q = 0; q < 8; q++) {
        const uint32_t v = src[q];
        if (v & 0x000000ffu) w |= 1u << (q * 4 + 0);
        if (v & 0x0000ff00u) w |= 1u << (q * 4 + 1);
        if (v & 0x00ff0000u) w |= 1u << (q * 4 + 2);
        if (v & 0xff000000u) w |= 1u << (q * 4 + 3);
    }
    g_mbits[idx] = w;
}

// ---------------------------------------------------------------------------
// One launch packs Q,K,V and all 4 weights to sigma-paired half2 words.
// ---------------------------------------------------------------------------
__global__ void pack_all(const float* __restrict__ Q, const float* __restrict__ K,
                         const float* __restrict__ V, const float* __restrict__ WQ,
                         const float* __restrict__ WK, const float* __restrict__ WV,
                         const float* __restrict__ Wo)
{
    const int blk = blockIdx.x;
    const float* src; uint32_t* dst; int base;
    if      (blk < 1024) { src = Q;  dst = g_Qh;    base = blk; }
    else if (blk < 2048) { src = K;  dst = g_Kh;    base = blk - 1024; }
    else if (blk < 3072) { src = V;  dst = g_Vh;    base = blk - 2048; }
    else if (blk < 3328) { src = WQ; dst = g_Wh[0]; base = blk - 3072; }
    else if (blk < 3584) { src = WK; dst = g_Wh[1]; base = blk - 3328; }
    else if (blk < 3840) { src = WV; dst = g_Wh[2]; base = blk - 3584; }
    else                 { src = Wo; dst = g_Wh[3]; base = blk - 3840; }
    const int idx = base * 256 + threadIdx.x;
    const float* s = src + (size_t)idx * 16;
    uint32_t w[8];
#pragma unroll
    for (int j = 0; j < 8; j++) {
        const float2 v = *(const float2*)(s + 2 * j);
        w[j] = h2pack(v.x, v.y);
    }
    uint4* d = (uint4*)(dst + (size_t)idx * 8);
    d[0] = make_uint4(w[0], w[4], w[1], w[5]);
    d[1] = make_uint4(w[2], w[6], w[3], w[7]);
}

// ---------------------------------------------------------------------------
// Projection GEMM body (pure-half operands, cp.async double-buffered).
// ---------------------------------------------------------------------------
#define PW 20
#define TILE_W (128*PW)

__device__ __forceinline__ void proj_body(
    uint32_t* sm, const uint32_t* __restrict__ Ah, const uint32_t* __restrict__ Wh,
    const float* __restrict__ bias, void* __restrict__ outv, int mode)
{
    const int tid = threadIdx.x;
    const int m0 = blockIdx.y * 128, n0 = blockIdx.x * 128;
    const int lane = tid & 31, warp = tid >> 5;
    const int wm = (warp & 3) * 32, wn = (warp >> 2) * 64;
    const int g = lane >> 2, t = lane & 3;
    const int row = tid >> 1;
    const int e = tid & 1;

    const uint32_t sbase = (uint32_t)__cvta_generic_to_shared(sm);
    const uint32_t* As_src = Ah + (size_t)(m0 + row) * 512 + e * 8;
    const uint32_t* Ws_src = Wh + (size_t)(n0 + row) * 512 + e * 8;
    const uint32_t dA = sbase + (uint32_t)(row * PW + e * 8) * 4;
    const uint32_t dB = dA + TILE_W * 4;

    auto stage = [&](int tile, int buf) {
        const uint32_t off = (uint32_t)(buf * 2 * TILE_W) * 4;
        const uint32_t* a = As_src + tile * 16;
        const uint32_t* w = Ws_src + tile * 16;
        cp16(dA + off, a);
        cp16(dA + off + 16, a + 4);
        cp16(dB + off, w);
        cp16(dB + off + 16, w + 4);
    };

    float c[2][8][4] = {};

    stage(0, 0); cp_commit();
    for (int tl = 0; tl < 32; tl++) {
        if (tl + 1 < 32) { stage(tl + 1, (tl + 1) & 1); cp_commit(); cp_wait<1>(); }
        else             { cp_wait<0>(); }
        __syncthreads();
        const uint32_t* As = sm + (tl & 1) * 2 * TILE_W;
        const uint32_t* Bs = As + TILE_W;
#pragma unroll
        for (int ks = 0; ks < 2; ks++) {
            const int kb = ks * 8 + 2 * t;
            uint32_t af[2][4], bf[8][2];
#pragma unroll
            for (int mi = 0; mi < 2; mi++) {
                const int r = wm + mi * 16 + g;
                const uint2 x = *(const uint2*)&As[r * PW + kb];
                const uint2 y = *(const uint2*)&As[(r + 8) * PW + kb];
                af[mi][0] = x.x; af[mi][2] = x.y;
                af[mi][1] = y.x; af[mi][3] = y.y;
            }
#pragma unroll
            for (int ni = 0; ni < 8; ni++) {
                const uint2 z = *(const uint2*)&Bs[(wn + ni * 8 + g) * PW + kb];
                bf[ni][0] = z.x; bf[ni][1] = z.y;
            }
#pragma unroll
            for (int mi = 0; mi < 2; mi++)
#pragma unroll
                for (int ni = 0; ni < 8; ni++)
                    mma_f16(c[mi][ni], af[mi], bf[ni]);
        }
        __syncthreads();
    }

#pragma unroll
    for (int mi = 0; mi < 2; mi++) {
#pragma unroll
        for (int rr = 0; rr < 2; rr++) {
            const int m = m0 + wm + mi * 16 + g + rr * 8;
            const int b_ = m >> 11, s = m & 2047;
#pragma unroll
            for (int ni = 0; ni < 8; ni++) {
                const int n = n0 + wn + ni * 8 + 2 * t;
                const float v0 = c[mi][ni][rr * 2 + 0] + bias[n];
                const float v1 = c[mi][ni][rr * 2 + 1] + bias[n + 1];
                if (mode == 0) {
                    *(float2*)&((float*)outv)[(size_t)m * 1024 + n] = make_float2(v0, v1);
                } else if (mode == 1) {
                    const int h = n >> 6;
                    const int ni_l = (n & 63) >> 3;
                    const int widx = (ni_l >> 1) * 8 + 2 * t + (ni_l & 1);
                    ((uint32_t*)outv)[((size_t)(b_ * 16 + h) * 2048 + s) * 32 + widx] =
                        h2pack(v0, v1);
                } else {
                    const int h = n >> 6;
                    const int dn = n & 63;
                    const int sw = (s >> 4) * 16 + sigma8((s & 15) >> 1) * 2 + (s & 1);
                    __half* vh = (__half*)outv;
                    vh[((size_t)(b_ * 16 + h) * 64 + dn) * 2048 + sw]     = __float2half_rn(v0);
                    vh[((size_t)(b_ * 16 + h) * 64 + dn + 1) * 2048 + sw] = __float2half_rn(v1);
                }
            }
        }
    }
}

__global__ void __launch_bounds__(256, 2) proj_qkv(
    const float* __restrict__ WQb, const float* __restrict__ WKb,
    const float* __restrict__ WVb)
{
    __shared__ uint32_t sh[4 * TILE_W];
    const int z = blockIdx.z;
    if (z == 0)      proj_body(sh, g_Qh, g_Wh[0], WQb, (void*)g_q, 1);
    else if (z == 1) proj_body(sh, g_Kh, g_Wh[1], WKb, (void*)g_k, 1);
    else             proj_body(sh, g_Vh, g_Wh[2], WVb, (void*)g_vT, 2);
}

__global__ void __launch_bounds__(256, 2) proj_out(
    const float* __restrict__ Wob, float* __restrict__ out)
{
    __shared__ uint32_t sh[4 * TILE_W];
    proj_body(sh, g_attnh, g_Wh[3], Wob, (void*)out, 0);
}

// ---------------------------------------------------------------------------
// Fused attention: 128-key staged chunks (two 64-key sub-tiles per stage).
// Pass A: depth-3 cp.async ring over 4 K buffers.  Pass B: K+V double-buffered.
// 4 x 5120-word buffers = 80 KB dynamic smem.
// ---------------------------------------------------------------------------
#define NCH2 16               // chunks of 128 keys
#define BUFW 5120             // words per buffer slot
#define FA_SMEM_BYTES (4*BUFW*4)   // 81920

__global__ void __launch_bounds__(256, 2) fused_attn(float* __restrict__ P)
{
    extern __shared__ uint32_t sm[];
    const int tid = threadIdx.x;
    const int lane = tid & 31, warp = tid >> 5;
    const int g = lane >> 2, t = lane & 3;
    const int bh = blockIdx.y;
    const int i0 = blockIdx.x * 128;
    const int b_ = bh >> 4, h = bh & 15;
    const int wm = warp * 16;
    const int row0 = i0 + wm + g;

    const uint32_t* Kg = g_k + (size_t)bh * SSEQ * 32;
    const uint32_t* Vg = g_vT + (size_t)bh * DK * 1024;
    float* Pg = P + (size_t)bh * SSEQ * SSEQ;
    const uint32_t* mb0 = g_mbits + ((size_t)b_ * SSEQ + row0) * 64;
    const uint32_t* mb1 = mb0 + (size_t)8 * 64;

    const uint32_t sbase = (uint32_t)__cvta_generic_to_shared(sm);

    // stage 128 keys x 32 words of K into buffer slot (stride 40)
    auto stageK_to = [&](int c, int buf) {
        const uint32_t dbase = sbase + (uint32_t)(buf * BUFW) * 4;
        const uint32_t* src = Kg + (size_t)c * 4096;
#pragma unroll
        for (int s = 0; s < 4; s++) {
            const int idx = tid + s * 256;
            const int key = idx >> 3, seg = idx & 7;
            cp16(dbase + (uint32_t)(key * 40 + seg * 4) * 4, src + key * 32 + seg * 4);
        }
    };
    // stage 64 d-rows x 64 words of V (128 keys) into buffer slot (stride 72)
    auto stageV_to = [&](int c, int buf) {
        const uint32_t dbase = sbase + (uint32_t)(buf * BUFW) * 4;
#pragma unroll
        for (int s = 0; s < 4; s++) {
            const int idx = tid + s * 256;
            const int d = idx >> 4, seg = idx & 15;
            cp16(dbase + (uint32_t)(d * 72 + seg * 4) * 4,
                 Vg + (size_t)d * 1024 + c * 64 + seg * 4);
        }
    };

    // Q fragments -> registers, once
    uint32_t qf[4][4];
#pragma unroll
    for (int ks = 0; ks < 4; ks++) {
        const uint2 qa = *(const uint2*)&g_q[((size_t)bh * SSEQ + row0) * 32 + ks * 8 + 2 * t];
        const uint2 qb = *(const uint2*)&g_q[((size_t)bh * SSEQ + row0 + 8) * 32 + ks * 8 + 2 * t];
        qf[ks][0] = qa.x; qf[ks][2] = qa.y;
        qf[ks][1] = qb.x; qf[ks][3] = qb.y;
    }

    // QK^T over a 64-key half of a staged 128-key chunk
    auto qk_half = [&](const uint32_t* Kb, int half, float cc[8][4]) {
#pragma unroll
        for (int ks = 0; ks < 4; ks++) {
            const int kb = ks * 8 + 2 * t;
#pragma unroll
            for (int nt = 0; nt < 8; nt++) {
                const uint2 kv = *(const uint2*)&Kb[(half * 64 + nt * 8 + g) * 40 + kb];
                uint32_t bb[2] = { kv.x, kv.y };
                mma_f16(cc[nt], qf[ks], bb);
            }
        }
    };

    // ================= PASS A: row sums (depth-3 ring over 4 buffers) ======
    float l0 = 0.f, l1 = 0.f;
    stageK_to(0, 0); cp_commit();
    stageK_to(1, 1); cp_commit();
    stageK_to(2, 2); cp_commit();
    for (int c = 0; c < NCH2; c++) {
        if (c + 3 < NCH2) { stageK_to(c + 3, (c + 3) & 3); cp_commit(); cp_wait<3>(); }
        else              { cp_wait<0>(); }
        __syncthreads();
        const uint32_t* Kb = sm + (c & 3) * BUFW;
#pragma unroll
        for (int half = 0; half < 2; half++) {
            float cc[8][4] = {};
            qk_half(Kb, half, cc);
            const uint2 w0 = *(const uint2*)(mb0 + c * 4 + half * 2);
            const uint2 w1 = *(const uint2*)(mb1 + c * 4 + half * 2);
#pragma unroll
            for (int nt = 0; nt < 8; nt++) {
                const int sh = (nt * 8) & 31;
                const uint32_t m0w = (nt < 4) ? w0.x : w0.y;
                const uint32_t m1w = (nt < 4) ? w1.x : w1.y;
                l0 += ((m0w >> (sh + 2 * t))     & 1) ? 0.f : __expf(cc[nt][0] * 0.125f);
                l0 += ((m0w >> (sh + 2 * t + 1)) & 1) ? 0.f : __expf(cc[nt][1] * 0.125f);
                l1 += ((m1w >> (sh + 2 * t))     & 1) ? 0.f : __expf(cc[nt][2] * 0.125f);
                l1 += ((m1w >> (sh + 2 * t + 1)) & 1) ? 0.f : __expf(cc[nt][3] * 0.125f);
            }
        }
        __syncthreads();
    }
    l0 += __shfl_xor_sync(0xffffffffu, l0, 1);
    l0 += __shfl_xor_sync(0xffffffffu, l0, 2);
    l1 += __shfl_xor_sync(0xffffffffu, l1, 1);
    l1 += __shfl_xor_sync(0xffffffffu, l1, 2);
    const float inv0 = 1.f / l0, inv1 = 1.f / l1;

    // ================= PASS B: normalize + write P + PV ====================
    float oacc[8][4] = {};
    stageK_to(0, 0); stageV_to(0, 2); cp_commit();
    for (int c = 0; c < NCH2; c++) {
        if (c + 1 < NCH2) {
            stageK_to(c + 1, (c + 1) & 1);
            stageV_to(c + 1, 2 + ((c + 1) & 1));
            cp_commit(); cp_wait<1>();
        } else {
            cp_wait<0>();
        }
        __syncthreads();
        const uint32_t* Kb = sm + (c & 1) * BUFW;
        const uint32_t* Vb = sm + (2 + (c & 1)) * BUFW;
#pragma unroll
        for (int half = 0; half < 2; half++) {
            float cc[8][4] = {};
            qk_half(Kb, half, cc);
            const int jc = c * 128 + half * 64;
            const uint2 w0 = *(const uint2*)(mb0 + c * 4 + half * 2);
            const uint2 w1 = *(const uint2*)(mb1 + c * 4 + half * 2);
#pragma unroll
            for (int nt = 0; nt < 8; nt++) {
                const int sh = (nt * 8) & 31;
                const uint32_t m0w = (nt < 4) ? w0.x : w0.y;
                const uint32_t m1w = (nt < 4) ? w1.x : w1.y;
                cc[nt][0] = ((m0w >> (sh + 2 * t))     & 1) ? 0.f : __expf(cc[nt][0] * 0.125f) * inv0;
                cc[nt][1] = ((m0w >> (sh + 2 * t + 1)) & 1) ? 0.f : __expf(cc[nt][1] * 0.125f) * inv0;
                cc[nt][2] = ((m1w >> (sh + 2 * t))     & 1) ? 0.f : __expf(cc[nt][2] * 0.125f) * inv1;
                cc[nt][3] = ((m1w >> (sh + 2 * t + 1)) & 1) ? 0.f : __expf(cc[nt][3] * 0.125f) * inv1;
                *(float2*)&Pg[(size_t)row0 * SSEQ + jc + nt * 8 + 2 * t] =
                    make_float2(cc[nt][0], cc[nt][1]);
                *(float2*)&Pg[(size_t)(row0 + 8) * SSEQ + jc + nt * 8 + 2 * t] =
                    make_float2(cc[nt][2], cc[nt][3]);
            }
            // PV: a-frags from c-frags; V keys for this half at word offset half*32
#pragma unroll
            for (int ks = 0; ks < 4; ks++) {
                uint32_t a[4] = {
                    h2pack(cc[2*ks][0],   cc[2*ks][1]),
                    h2pack(cc[2*ks][2],   cc[2*ks][3]),
                    h2pack(cc[2*ks+1][0], cc[2*ks+1][1]),
                    h2pack(cc[2*ks+1][2], cc[2*ks+1][3])
                };
                const int kb = half * 32 + ks * 8 + 2 * t;
#pragma unroll
                for (int nt = 0; nt < 8; nt++) {
                    const uint2 vv = *(const uint2*)&Vb[(nt * 8 + g) * 72 + kb];
                    uint32_t bb[2] = { vv.x, vv.y };
                    mma_f16(oacc[nt], a, bb);
                }
            }
        }
        __syncthreads();
    }

    // epilogue: packed merged attn
#pragma unroll
    for (int nt = 0; nt < 8; nt++) {
        const int widx = (h * 4 + (nt >> 1)) * 8 + 2 * t + (nt & 1);
        g_attnh[((size_t)(b_ * SSEQ + row0)) * 512 + widx]     = h2pack(oacc[nt][0], oacc[nt][1]);
        g_attnh[((size_t)(b_ * SSEQ + row0 + 8)) * 512 + widx] = h2pack(oacc[nt][2], oacc[nt][3]);
    }
}

// ---------------------------------------------------------------------------
extern "C" void kernel_launch(void* const* d_in, const int* in_sizes, int n_in,
                              void* d_out, int out_size)
{
    const float* Q   = (const float*)d_in[0];
    const float* K   = (const float*)d_in[1];
    const float* V   = (const float*)d_in[2];
    const unsigned char* mask = (const unsigned char*)d_in[3];
    const float* WQw = (const float*)d_in[4];
    const float* WQb = (const float*)d_in[5];
    const float* WKw = (const float*)d_in[6];
    const float* WKb = (const float*)d_in[7];
    const float* WVw = (const float*)d_in[8];
    const float* WVb = (const float*)d_in[9];
    const float* Wow = (const float*)d_in[10];
    const float* Wob = (const float*)d_in[11];

    float* out   = (float*)d_out;                       // [B,S,D]
    float* attnw = out + (size_t)MTOT * DM;             // [B,H,S,S]

    cudaFuncSetAttribute(fused_attn, cudaFuncAttributeMaxDynamicSharedMemorySize,
                         FA_SMEM_BYTES);

    maskbits_kernel<<<(BB * SSEQ * (SSEQ / 32)) / 256, 256>>>(mask);
    pack_all<<<4096, 256>>>(Q, K, V, WQw, WKw, WVw, Wow);

    proj_qkv<<<dim3(8, 32, 3), 256>>>(WQb, WKb, WVb);

    fused_attn<<<dim3(16, 32), 256, FA_SMEM_BYTES>>>(attnw);

    proj_out<<<dim3(8, 32), 256>>>(Wob, out);
}

// round 12
// speedup vs baseline: 2.1349x; 1.0709x over previous
#include <cuda_runtime.h>
#include <cuda_fp16.h>
#include <cstdint>
#include <cstddef>

#define DM 1024
#define NH 16
#define DK 64
#define BB 2
#define SSEQ 2048
#define MTOT (BB*SSEQ)     // 4096
#define BH (BB*NH)         // 32

#define EXPC 0.18033688011112042f   // 0.125 * log2(e)

// Packed half2 words (uint32), k/d sigma-paired within 8-word (16-half) groups.
__device__ uint32_t g_Qh[(size_t)MTOT*512];
__device__ uint32_t g_Kh[(size_t)MTOT*512];
__device__ uint32_t g_Vh[(size_t)MTOT*512];
__device__ uint32_t g_Wh[4][(size_t)DM*512];
__device__ uint32_t g_q[(size_t)BH*SSEQ*32];   // projected q [bh][s][32w]
__device__ uint32_t g_k[(size_t)BH*SSEQ*32];
__device__ uint32_t g_vT[(size_t)BH*DK*1024];  // [bh][64 d][1024w keys sigma'd]
__device__ uint32_t g_attnh[(size_t)MTOT*512]; // merged attn, packed
__device__ uint32_t g_mbits[(size_t)BB*SSEQ*(SSEQ/32)];

// ---------------------------------------------------------------------------
__device__ __forceinline__ uint32_t h2pack(float a, float b) {
    __half2 h = __floats2half2_rn(a, b);
    return *(uint32_t*)&h;
}
__device__ __forceinline__ void mma_f16(float* c, const uint32_t* a, const uint32_t* b) {
    asm volatile(
        "mma.sync.aligned.m16n8k16.row.col.f32.f16.f16.f32 "
        "{%0,%1,%2,%3}, {%4,%5,%6,%7}, {%8,%9}, {%0,%1,%2,%3};\n"
        : "+f"(c[0]), "+f"(c[1]), "+f"(c[2]), "+f"(c[3])
        : "r"(a[0]), "r"(a[1]), "r"(a[2]), "r"(a[3]), "r"(b[0]), "r"(b[1]));
}
__device__ __forceinline__ void cp16(uint32_t d, const void* s) {
    asm volatile("cp.async.ca.shared.global [%0], [%1], 16;\n" :: "r"(d), "l"(s));
}
__device__ __forceinline__ void cp_commit() { asm volatile("cp.async.commit_group;\n"); }
template<int N> __device__ __forceinline__ void cp_wait() {
    asm volatile("cp.async.wait_group %0;\n" :: "n"(N));
}
__device__ __host__ __forceinline__ int sigma8(int j) {
    return (j < 4) ? 2 * j : 2 * (j - 4) + 1;
}

// ---------------------------------------------------------------------------
__global__ void maskbits_kernel(const unsigned char* __restrict__ mask)
{
    const int idx = blockIdx.x * 256 + threadIdx.x;
    const uint32_t* src = (const uint32_t*)(mask + (size_t)idx * 32);
    uint32_t w = 0;
#pragma unroll
    for (int q = 0; q < 8; q++) {
        const uint32_t v = src[q];
        if (v & 0x000000ffu) w |= 1u << (q * 4 + 0);
        if (v & 0x0000ff00u) w |= 1u << (q * 4 + 1);
        if (v & 0x00ff0000u) w |= 1u << (q * 4 + 2);
        if (v & 0xff000000u) w |= 1u << (q * 4 + 3);
    }
    g_mbits[idx] = w;
}

// ---------------------------------------------------------------------------
__global__ void pack_all(const float* __restrict__ Q, const float* __restrict__ K,
                         const float* __restrict__ V, const float* __restrict__ WQ,
                         const float* __restrict__ WK, const float* __restrict__ WV,
                         const float* __restrict__ Wo)
{
    const int blk = blockIdx.x;
    const float* src; uint32_t* dst; int base;
    if      (blk < 1024) { src = Q;  dst = g_Qh;    base = blk; }
    else if (blk < 2048) { src = K;  dst = g_Kh;    base = blk - 1024; }
    else if (blk < 3072) { src = V;  dst = g_Vh;    base = blk - 2048; }
    else if (blk < 3328) { src = WQ; dst = g_Wh[0]; base = blk - 3072; }
    else if (blk < 3584) { src = WK; dst = g_Wh[1]; base = blk - 3328; }
    else if (blk < 3840) { src = WV; dst = g_Wh[2]; base = blk - 3584; }
    else                 { src = Wo; dst = g_Wh[3]; base = blk - 3840; }
    const int idx = base * 256 + threadIdx.x;
    const float* s = src + (size_t)idx * 16;
    uint32_t w[8];
#pragma unroll
    for (int j = 0; j < 8; j++) {
        const float2 v = *(const float2*)(s + 2 * j);
        w[j] = h2pack(v.x, v.y);
    }
    uint4* d = (uint4*)(dst + (size_t)idx * 8);
    d[0] = make_uint4(w[0], w[4], w[1], w[5]);
    d[1] = make_uint4(w[2], w[6], w[3], w[7]);
}

// ---------------------------------------------------------------------------
// Projection GEMM body (pure-half operands, cp.async double-buffered).
// ---------------------------------------------------------------------------
#define PW 20
#define TILE_W (128*PW)

__device__ __forceinline__ void proj_body(
    uint32_t* sm, const uint32_t* __restrict__ Ah, const uint32_t* __restrict__ Wh,
    const float* __restrict__ bias, void* __restrict__ outv, int mode)
{
    const int tid = threadIdx.x;
    const int m0 = blockIdx.y * 128, n0 = blockIdx.x * 128;
    const int lane = tid & 31, warp = tid >> 5;
    const int wm = (warp & 3) * 32, wn = (warp >> 2) * 64;
    const int g = lane >> 2, t = lane & 3;
    const int row = tid >> 1;
    const int e = tid & 1;

    const uint32_t sbase = (uint32_t)__cvta_generic_to_shared(sm);
    const uint32_t* As_src = Ah + (size_t)(m0 + row) * 512 + e * 8;
    const uint32_t* Ws_src = Wh + (size_t)(n0 + row) * 512 + e * 8;
    const uint32_t dA = sbase + (uint32_t)(row * PW + e * 8) * 4;
    const uint32_t dB = dA + TILE_W * 4;

    auto stage = [&](int tile, int buf) {
        const uint32_t off = (uint32_t)(buf * 2 * TILE_W) * 4;
        const uint32_t* a = As_src + tile * 16;
        const uint32_t* w = Ws_src + tile * 16;
        cp16(dA + off, a);
        cp16(dA + off + 16, a + 4);
        cp16(dB + off, w);
        cp16(dB + off + 16, w + 4);
    };

    float c[2][8][4] = {};

    stage(0, 0); cp_commit();
    for (int tl = 0; tl < 32; tl++) {
        if (tl + 1 < 32) { stage(tl + 1, (tl + 1) & 1); cp_commit(); cp_wait<1>(); }
        else             { cp_wait<0>(); }
        __syncthreads();
        const uint32_t* As = sm + (tl & 1) * 2 * TILE_W;
        const uint32_t* Bs = As + TILE_W;
#pragma unroll
        for (int ks = 0; ks < 2; ks++) {
            const int kb = ks * 8 + 2 * t;
            uint32_t af[2][4], bf[8][2];
#pragma unroll
            for (int mi = 0; mi < 2; mi++) {
                const int r = wm + mi * 16 + g;
                const uint2 x = *(const uint2*)&As[r * PW + kb];
                const uint2 y = *(const uint2*)&As[(r + 8) * PW + kb];
                af[mi][0] = x.x; af[mi][2] = x.y;
                af[mi][1] = y.x; af[mi][3] = y.y;
            }
#pragma unroll
            for (int ni = 0; ni < 8; ni++) {
                const uint2 z = *(const uint2*)&Bs[(wn + ni * 8 + g) * PW + kb];
                bf[ni][0] = z.x; bf[ni][1] = z.y;
            }
#pragma unroll
            for (int mi = 0; mi < 2; mi++)
#pragma unroll
                for (int ni = 0; ni < 8; ni++)
                    mma_f16(c[mi][ni], af[mi], bf[ni]);
        }
        __syncthreads();
    }

#pragma unroll
    for (int mi = 0; mi < 2; mi++) {
#pragma unroll
        for (int rr = 0; rr < 2; rr++) {
            const int m = m0 + wm + mi * 16 + g + rr * 8;
            const int b_ = m >> 11, s = m & 2047;
#pragma unroll
            for (int ni = 0; ni < 8; ni++) {
                const int n = n0 + wn + ni * 8 + 2 * t;
                const float v0 = c[mi][ni][rr * 2 + 0] + bias[n];
                const float v1 = c[mi][ni][rr * 2 + 1] + bias[n + 1];
                if (mode == 0) {
                    *(float2*)&((float*)outv)[(size_t)m * 1024 + n] = make_float2(v0, v1);
                } else if (mode == 1) {
                    const int h = n >> 6;
                    const int ni_l = (n & 63) >> 3;
                    const int widx = (ni_l >> 1) * 8 + 2 * t + (ni_l & 1);
                    ((uint32_t*)outv)[((size_t)(b_ * 16 + h) * 2048 + s) * 32 + widx] =
                        h2pack(v0, v1);
                } else {
                    const int h = n >> 6;
                    const int dn = n & 63;
                    const int sw = (s >> 4) * 16 + sigma8((s & 15) >> 1) * 2 + (s & 1);
                    __half* vh = (__half*)outv;
                    vh[((size_t)(b_ * 16 + h) * 64 + dn) * 2048 + sw]     = __float2half_rn(v0);
                    vh[((size_t)(b_ * 16 + h) * 64 + dn + 1) * 2048 + sw] = __float2half_rn(v1);
                }
            }
        }
    }
}

__global__ void __launch_bounds__(256, 2) proj_qkv(
    const float* __restrict__ WQb, const float* __restrict__ WKb,
    const float* __restrict__ WVb)
{
    __shared__ uint32_t sh[4 * TILE_W];
    const int z = blockIdx.z;
    if (z == 0)      proj_body(sh, g_Qh, g_Wh[0], WQb, (void*)g_q, 1);
    else if (z == 1) proj_body(sh, g_Kh, g_Wh[1], WKb, (void*)g_k, 1);
    else             proj_body(sh, g_Vh, g_Wh[2], WVb, (void*)g_vT, 2);
}

__global__ void __launch_bounds__(256, 2) proj_out(
    const float* __restrict__ Wob, float* __restrict__ out)
{
    __shared__ uint32_t sh[4 * TILE_W];
    proj_body(sh, g_attnh, g_Wh[3], Wob, (void*)out, 0);
}

// ---------------------------------------------------------------------------
// Fused attention: 128-key staged chunks; mask fast path when all 64 bits
// of a chunk row-pair are zero (uniform for the all-false mask case).
// ---------------------------------------------------------------------------
#define NCH2 16
#define BUFW 5120
#define FA_SMEM_BYTES (4*BUFW*4)   // 81920

__global__ void __launch_bounds__(256, 2) fused_attn(float* __restrict__ P)
{
    extern __shared__ uint32_t sm[];
    const int tid = threadIdx.x;
    const int lane = tid & 31, warp = tid >> 5;
    const int g = lane >> 2, t = lane & 3;
    const int bh = blockIdx.y;
    const int i0 = blockIdx.x * 128;
    const int b_ = bh >> 4, h = bh & 15;
    const int wm = warp * 16;
    const int row0 = i0 + wm + g;

    const uint32_t* Kg = g_k + (size_t)bh * SSEQ * 32;
    const uint32_t* Vg = g_vT + (size_t)bh * DK * 1024;
    float* Pg = P + (size_t)bh * SSEQ * SSEQ;
    const uint32_t* mb0 = g_mbits + ((size_t)b_ * SSEQ + row0) * 64;
    const uint32_t* mb1 = mb0 + (size_t)8 * 64;

    const uint32_t sbase = (uint32_t)__cvta_generic_to_shared(sm);

    auto stageK_to = [&](int c, int buf) {
        const uint32_t dbase = sbase + (uint32_t)(buf * BUFW) * 4;
        const uint32_t* src = Kg + (size_t)c * 4096;
#pragma unroll
        for (int s = 0; s < 4; s++) {
            const int idx = tid + s * 256;
            const int key = idx >> 3, seg = idx & 7;
            cp16(dbase + (uint32_t)(key * 40 + seg * 4) * 4, src + key * 32 + seg * 4);
        }
    };
    auto stageV_to = [&](int c, int buf) {
        const uint32_t dbase = sbase + (uint32_t)(buf * BUFW) * 4;
#pragma unroll
        for (int s = 0; s < 4; s++) {
            const int idx = tid + s * 256;
            const int d = idx >> 4, seg = idx & 15;
            cp16(dbase + (uint32_t)(d * 72 + seg * 4) * 4,
                 Vg + (size_t)d * 1024 + c * 64 + seg * 4);
        }
    };

    uint32_t qf[4][4];
#pragma unroll
    for (int ks = 0; ks < 4; ks++) {
        const uint2 qa = *(const uint2*)&g_q[((size_t)bh * SSEQ + row0) * 32 + ks * 8 + 2 * t];
        const uint2 qb = *(const uint2*)&g_q[((size_t)bh * SSEQ + row0 + 8) * 32 + ks * 8 + 2 * t];
        qf[ks][0] = qa.x; qf[ks][2] = qa.y;
        qf[ks][1] = qb.x; qf[ks][3] = qb.y;
    }

    auto qk_half = [&](const uint32_t* Kb, int half, float cc[8][4]) {
#pragma unroll
        for (int ks = 0; ks < 4; ks++) {
            const int kb = ks * 8 + 2 * t;
#pragma unroll
            for (int nt = 0; nt < 8; nt++) {
                const uint2 kv = *(const uint2*)&Kb[(half * 64 + nt * 8 + g) * 40 + kb];
                uint32_t bb[2] = { kv.x, kv.y };
                mma_f16(cc[nt], qf[ks], bb);
            }
        }
    };

    // ================= PASS A: row sums =================
    float l0 = 0.f, l1 = 0.f;
    stageK_to(0, 0); cp_commit();
    stageK_to(1, 1); cp_commit();
    stageK_to(2, 2); cp_commit();
    for (int c = 0; c < NCH2; c++) {
        if (c + 3 < NCH2) { stageK_to(c + 3, (c + 3) & 3); cp_commit(); cp_wait<3>(); }
        else              { cp_wait<0>(); }
        __syncthreads();
        const uint32_t* Kb = sm + (c & 3) * BUFW;
#pragma unroll
        for (int half = 0; half < 2; half++) {
            float cc[8][4] = {};
            qk_half(Kb, half, cc);
            const uint2 w0 = *(const uint2*)(mb0 + c * 4 + half * 2);
            const uint2 w1 = *(const uint2*)(mb1 + c * 4 + half * 2);
            if ((w0.x | w0.y | w1.x | w1.y) == 0u) {
#pragma unroll
                for (int nt = 0; nt < 8; nt++) {
                    l0 += exp2f(cc[nt][0] * EXPC) + exp2f(cc[nt][1] * EXPC);
                    l1 += exp2f(cc[nt][2] * EXPC) + exp2f(cc[nt][3] * EXPC);
                }
            } else {
#pragma unroll
                for (int nt = 0; nt < 8; nt++) {
                    const int sh = (nt * 8) & 31;
                    const uint32_t m0w = (nt < 4) ? w0.x : w0.y;
                    const uint32_t m1w = (nt < 4) ? w1.x : w1.y;
                    l0 += ((m0w >> (sh + 2 * t))     & 1) ? 0.f : exp2f(cc[nt][0] * EXPC);
                    l0 += ((m0w >> (sh + 2 * t + 1)) & 1) ? 0.f : exp2f(cc[nt][1] * EXPC);
                    l1 += ((m1w >> (sh + 2 * t))     & 1) ? 0.f : exp2f(cc[nt][2] * EXPC);
                    l1 += ((m1w >> (sh + 2 * t + 1)) & 1) ? 0.f : exp2f(cc[nt][3] * EXPC);
                }
            }
        }
        __syncthreads();
    }
    l0 += __shfl_xor_sync(0xffffffffu, l0, 1);
    l0 += __shfl_xor_sync(0xffffffffu, l0, 2);
    l1 += __shfl_xor_sync(0xffffffffu, l1, 1);
    l1 += __shfl_xor_sync(0xffffffffu, l1, 2);
    const float inv0 = 1.f / l0, inv1 = 1.f / l1;

    // ================= PASS B: normalize + write P + PV ====================
    float oacc[8][4] = {};
    stageK_to(0, 0); stageV_to(0, 2); cp_commit();
    for (int c = 0; c < NCH2; c++) {
        if (c + 1 < NCH2) {
            stageK_to(c + 1, (c + 1) & 1);
            stageV_to(c + 1, 2 + ((c + 1) & 1));
            cp_commit(); cp_wait<1>();
        } else {
            cp_wait<0>();
        }
        __syncthreads();
        const uint32_t* Kb = sm + (c & 1) * BUFW;
        const uint32_t* Vb = sm + (2 + (c & 1)) * BUFW;
#pragma unroll
        for (int half = 0; half < 2; half++) {
            float cc[8][4] = {};
            qk_half(Kb, half, cc);
            const int jc = c * 128 + half * 64;
            float* pr0 = &Pg[(size_t)row0 * SSEQ + jc + 2 * t];
            float* pr1 = &Pg[(size_t)(row0 + 8) * SSEQ + jc + 2 * t];
            const uint2 w0 = *(const uint2*)(mb0 + c * 4 + half * 2);
            const uint2 w1 = *(const uint2*)(mb1 + c * 4 + half * 2);
            if ((w0.x | w0.y | w1.x | w1.y) == 0u) {
#pragma unroll
                for (int nt = 0; nt < 8; nt++) {
                    cc[nt][0] = exp2f(cc[nt][0] * EXPC) * inv0;
                    cc[nt][1] = exp2f(cc[nt][1] * EXPC) * inv0;
                    cc[nt][2] = exp2f(cc[nt][2] * EXPC) * inv1;
                    cc[nt][3] = exp2f(cc[nt][3] * EXPC) * inv1;
                    *(float2*)&pr0[nt * 8] = make_float2(cc[nt][0], cc[nt][1]);
                    *(float2*)&pr1[nt * 8] = make_float2(cc[nt][2], cc[nt][3]);
                }
            } else {
#pragma unroll
                for (int nt = 0; nt < 8; nt++) {
                    const int sh = (nt * 8) & 31;
                    const uint32_t m0w = (nt < 4) ? w0.x : w0.y;
                    const uint32_t m1w = (nt < 4) ? w1.x : w1.y;
                    cc[nt][0] = ((m0w >> (sh + 2 * t))     & 1) ? 0.f : exp2f(cc[nt][0] * EXPC) * inv0;
                    cc[nt][1] = ((m0w >> (sh + 2 * t + 1)) & 1) ? 0.f : exp2f(cc[nt][1] * EXPC) * inv0;
                    cc[nt][2] = ((m1w >> (sh + 2 * t))     & 1) ? 0.f : exp2f(cc[nt][2] * EXPC) * inv1;
                    cc[nt][3] = ((m1w >> (sh + 2 * t + 1)) & 1) ? 0.f : exp2f(cc[nt][3] * EXPC) * inv1;
                    *(float2*)&pr0[nt * 8] = make_float2(cc[nt][0], cc[nt][1]);
                    *(float2*)&pr1[nt * 8] = make_float2(cc[nt][2], cc[nt][3]);
                }
            }
            // PV: a-frags from c-frags; V keys for this half at word offset half*32
#pragma unroll
            for (int ks = 0; ks < 4; ks++) {
                uint32_t a[4] = {
                    h2pack(cc[2*ks][0],   cc[2*ks][1]),
                    h2pack(cc[2*ks][2],   cc[2*ks][3]),
                    h2pack(cc[2*ks+1][0], cc[2*ks+1][1]),
                    h2pack(cc[2*ks+1][2], cc[2*ks+1][3])
                };
                const int kb = half * 32 + ks * 8 + 2 * t;
#pragma unroll
                for (int nt = 0; nt < 8; nt++) {
                    const uint2 vv = *(const uint2*)&Vb[(nt * 8 + g) * 72 + kb];
                    uint32_t bb[2] = { vv.x, vv.y };
                    mma_f16(oacc[nt], a, bb);
                }
            }
        }
        __syncthreads();
    }

    // epilogue: packed merged attn
#pragma unroll
    for (int nt = 0; nt < 8; nt++) {
        const int widx = (h * 4 + (nt >> 1)) * 8 + 2 * t + (nt & 1);
        g_attnh[((size_t)(b_ * SSEQ + row0)) * 512 + widx]     = h2pack(oacc[nt][0], oacc[nt][1]);
        g_attnh[((size_t)(b_ * SSEQ + row0 + 8)) * 512 + widx] = h2pack(oacc[nt][2], oacc[nt][3]);
    }
}

// ---------------------------------------------------------------------------
extern "C" void kernel_launch(void* const* d_in, const int* in_sizes, int n_in,
                              void* d_out, int out_size)
{
    const float* Q   = (const float*)d_in[0];
    const float* K   = (const float*)d_in[1];
    const float* V   = (const float*)d_in[2];
    const unsigned char* mask = (const unsigned char*)d_in[3];
    const float* WQw = (const float*)d_in[4];
    const float* WQb = (const float*)d_in[5];
    const float* WKw = (const float*)d_in[6];
    const float* WKb = (const float*)d_in[7];
    const float* WVw = (const float*)d_in[8];
    const float* WVb = (const float*)d_in[9];
    const float* Wow = (const float*)d_in[10];
    const float* Wob = (const float*)d_in[11];

    float* out   = (float*)d_out;                       // [B,S,D]
    float* attnw = out + (size_t)MTOT * DM;             // [B,H,S,S]

    cudaFuncSetAttribute(fused_attn, cudaFuncAttributeMaxDynamicSharedMemorySize,
                         FA_SMEM_BYTES);

    maskbits_kernel<<<(BB * SSEQ * (SSEQ / 32)) / 256, 256>>>(mask);
    pack_all<<<4096, 256>>>(Q, K, V, WQw, WKw, WVw, Wow);

    proj_qkv<<<dim3(8, 32, 3), 256>>>(WQb, WKb, WVb);

    fused_attn<<<dim3(16, 32), 256, FA_SMEM_BYTES>>>(attnw);

    proj_out<<<dim3(8, 32), 256>>>(Wob, out);
}

// round 15
// speedup vs baseline: 2.1920x; 1.0267x over previous
#include <cuda_runtime.h>
#include <cuda_fp16.h>
#include <cstdint>
#include <cstddef>

#define DM 1024
#define NH 16
#define DK 64
#define BB 2
#define SSEQ 2048
#define MTOT (BB*SSEQ)     // 4096
#define BH (BB*NH)         // 32

#define EXPC 0.18033688011112042f   // 0.125 * log2(e)

// Packed half2 words (uint32), k/d sigma-paired within 8-word (16-half) groups.
__device__ uint32_t g_Qh[(size_t)MTOT*512];
__device__ uint32_t g_Kh[(size_t)MTOT*512];
__device__ uint32_t g_Vh[(size_t)MTOT*512];
__device__ uint32_t g_Wh[4][(size_t)DM*512];
__device__ uint32_t g_q[(size_t)BH*SSEQ*32];   // projected q [bh][s][32w]
__device__ uint32_t g_k[(size_t)BH*SSEQ*32];
__device__ uint32_t g_vT[(size_t)BH*DK*1024];  // [bh][64 d][1024w keys sigma'd]
__device__ uint32_t g_attnh[(size_t)MTOT*512]; // merged attn, packed
__device__ uint32_t g_mbits[(size_t)BB*SSEQ*(SSEQ/32)];

// ---------------------------------------------------------------------------
__device__ __forceinline__ uint32_t h2pack(float a, float b) {
    __half2 h = __floats2half2_rn(a, b);
    return *(uint32_t*)&h;
}
__device__ __forceinline__ void mma_f16(float* c, const uint32_t* a, const uint32_t* b) {
    asm volatile(
        "mma.sync.aligned.m16n8k16.row.col.f32.f16.f16.f32 "
        "{%0,%1,%2,%3}, {%4,%5,%6,%7}, {%8,%9}, {%0,%1,%2,%3};\n"
        : "+f"(c[0]), "+f"(c[1]), "+f"(c[2]), "+f"(c[3])
        : "r"(a[0]), "r"(a[1]), "r"(a[2]), "r"(a[3]), "r"(b[0]), "r"(b[1]));
}
__device__ __forceinline__ void cp16(uint32_t d, const void* s) {
    asm volatile("cp.async.ca.shared.global [%0], [%1], 16;\n" :: "r"(d), "l"(s));
}
__device__ __forceinline__ void cp_commit() { asm volatile("cp.async.commit_group;\n"); }
template<int N> __device__ __forceinline__ void cp_wait() {
    asm volatile("cp.async.wait_group %0;\n" :: "n"(N));
}
__device__ __host__ __forceinline__ int sigma8(int j) {
    return (j < 4) ? 2 * j : 2 * (j - 4) + 1;
}

// ---------------------------------------------------------------------------
// pack_all: blocks [0,4096) pack Q,K,V,W*; blocks [4096,5120) build maskbits.
// ---------------------------------------------------------------------------
__global__ void pack_all(const float* __restrict__ Q, const float* __restrict__ K,
                         const float* __restrict__ V, const float* __restrict__ WQ,
                         const float* __restrict__ WK, const float* __restrict__ WV,
                         const float* __restrict__ Wo, const unsigned char* __restrict__ mask)
{
    const int blk = blockIdx.x;
    if (blk >= 4096) {
        const int idx = (blk - 4096) * 256 + threadIdx.x;
        const uint32_t* src = (const uint32_t*)(mask + (size_t)idx * 32);
        uint32_t w = 0;
#pragma unroll
        for (int q = 0; q < 8; q++) {
            const uint32_t v = src[q];
            if (v & 0x000000ffu) w |= 1u << (q * 4 + 0);
            if (v & 0x0000ff00u) w |= 1u << (q * 4 + 1);
            if (v & 0x00ff0000u) w |= 1u << (q * 4 + 2);
            if (v & 0xff000000u) w |= 1u << (q * 4 + 3);
        }
        g_mbits[idx] = w;
        return;
    }
    const float* src; uint32_t* dst; int base;
    if      (blk < 1024) { src = Q;  dst = g_Qh;    base = blk; }
    else if (blk < 2048) { src = K;  dst = g_Kh;    base = blk - 1024; }
    else if (blk < 3072) { src = V;  dst = g_Vh;    base = blk - 2048; }
    else if (blk < 3328) { src = WQ; dst = g_Wh[0]; base = blk - 3072; }
    else if (blk < 3584) { src = WK; dst = g_Wh[1]; base = blk - 3328; }
    else if (blk < 3840) { src = WV; dst = g_Wh[2]; base = blk - 3584; }
    else                 { src = Wo; dst = g_Wh[3]; base = blk - 3840; }
    const int idx = base * 256 + threadIdx.x;
    const float* s = src + (size_t)idx * 16;
    uint32_t w[8];
#pragma unroll
    for (int j = 0; j < 8; j++) {
        const float2 v = *(const float2*)(s + 2 * j);
        w[j] = h2pack(v.x, v.y);
    }
    uint4* d = (uint4*)(dst + (size_t)idx * 8);
    d[0] = make_uint4(w[0], w[4], w[1], w[5]);
    d[1] = make_uint4(w[2], w[6], w[3], w[7]);
}

// ---------------------------------------------------------------------------
// Projection GEMM: M=256 x N=128 tile, 512 threads (16 warps = 8m x 2n),
// warp tile 32x64, per-thread tile identical to R12 (bit-identical results).
// Dynamic smem: A bufs 2x5120w, B bufs 2x2560w = 61440 B.
// ---------------------------------------------------------------------------
#define PW 20
#define PJ_SMEM_W 15360
#define PJ_SMEM_BYTES (PJ_SMEM_W*4)

__device__ __forceinline__ void proj_body(
    const uint32_t* __restrict__ Ah, const uint32_t* __restrict__ Wh,
    const float* __restrict__ bias, void* __restrict__ outv, int mode)
{
    extern __shared__ uint32_t psm[];
    const int tid = threadIdx.x;
    const int m0 = blockIdx.y * 256, n0 = blockIdx.x * 128;
    const int lane = tid & 31, warp = tid >> 5;
    const int wm = (warp & 7) * 32, wn = (warp >> 3) * 64;
    const int g = lane >> 2, t = lane & 3;

    const uint32_t sbase = (uint32_t)__cvta_generic_to_shared(psm);
    // A staging: 256 rows x 16 words, thread -> (row = tid>>1, e = tid&1)
    const int arow = tid >> 1, ae = tid & 1;
    const uint32_t* Asrc = Ah + (size_t)(m0 + arow) * 512 + ae * 8;
    const uint32_t dAb = sbase + (uint32_t)(arow * PW + ae * 8) * 4;
    // B staging: 128 rows x 16 words, thread -> (row = tid>>2, seg = tid&3)
    const int brow = tid >> 2, bseg = tid & 3;
    const uint32_t* Wsrc = Wh + (size_t)(n0 + brow) * 512 + bseg * 4;
    const uint32_t dBb = sbase + (uint32_t)(10240 + brow * PW + bseg * 4) * 4;

    auto stage = [&](int tile, int buf) {
        const uint32_t aoff = (uint32_t)(buf * 5120) * 4;
        const uint32_t boff = (uint32_t)(buf * 2560) * 4;
        cp16(dAb + aoff, Asrc + tile * 16);
        cp16(dAb + aoff + 16, Asrc + tile * 16 + 4);
        cp16(dBb + boff, Wsrc + tile * 16);
    };

    float c[2][8][4] = {};

    stage(0, 0); cp_commit();
    for (int tl = 0; tl < 32; tl++) {
        cp_wait<0>();
        __syncthreads();
        if (tl + 1 < 32) { stage(tl + 1, (tl + 1) & 1); cp_commit(); }
        const uint32_t* As = psm + (tl & 1) * 5120;
        const uint32_t* Bs = psm + 10240 + (tl & 1) * 2560;
#pragma unroll
        for (int ks = 0; ks < 2; ks++) {
            const int kb = ks * 8 + 2 * t;
            uint32_t af[2][4], bf[8][2];
#pragma unroll
            for (int mi = 0; mi < 2; mi++) {
                const int r = wm + mi * 16 + g;
                const uint2 x = *(const uint2*)&As[r * PW + kb];
                const uint2 y = *(const uint2*)&As[(r + 8) * PW + kb];
                af[mi][0] = x.x; af[mi][2] = x.y;
                af[mi][1] = y.x; af[mi][3] = y.y;
            }
#pragma unroll
            for (int ni = 0; ni < 8; ni++) {
                const uint2 z = *(const uint2*)&Bs[(wn + ni * 8 + g) * PW + kb];
                bf[ni][0] = z.x; bf[ni][1] = z.y;
            }
#pragma unroll
            for (int mi = 0; mi < 2; mi++)
#pragma unroll
                for (int ni = 0; ni < 8; ni++)
                    mma_f16(c[mi][ni], af[mi], bf[ni]);
        }
        __syncthreads();
    }

#pragma unroll
    for (int mi = 0; mi < 2; mi++) {
#pragma unroll
        for (int rr = 0; rr < 2; rr++) {
            const int m = m0 + wm + mi * 16 + g + rr * 8;
            const int b_ = m >> 11, s = m & 2047;
#pragma unroll
            for (int ni = 0; ni < 8; ni++) {
                const int n = n0 + wn + ni * 8 + 2 * t;
                const float v0 = c[mi][ni][rr * 2 + 0] + bias[n];
                const float v1 = c[mi][ni][rr * 2 + 1] + bias[n + 1];
                if (mode == 0) {
                    *(float2*)&((float*)outv)[(size_t)m * 1024 + n] = make_float2(v0, v1);
                } else if (mode == 1) {
                    const int h = n >> 6;
                    const int ni_l = (n & 63) >> 3;
                    const int widx = (ni_l >> 1) * 8 + 2 * t + (ni_l & 1);
                    ((uint32_t*)outv)[((size_t)(b_ * 16 + h) * 2048 + s) * 32 + widx] =
                        h2pack(v0, v1);
                } else {
                    const int h = n >> 6;
                    const int dn = n & 63;
                    const int sw = (s >> 4) * 16 + sigma8((s & 15) >> 1) * 2 + (s & 1);
                    __half* vh = (__half*)outv;
                    vh[((size_t)(b_ * 16 + h) * 64 + dn) * 2048 + sw]     = __float2half_rn(v0);
                    vh[((size_t)(b_ * 16 + h) * 64 + dn + 1) * 2048 + sw] = __float2half_rn(v1);
                }
            }
        }
    }
}

__global__ void __launch_bounds__(512, 1) proj_qkv(
    const float* __restrict__ WQb, const float* __restrict__ WKb,
    const float* __restrict__ WVb)
{
    const int z = blockIdx.z;
    if (z == 0)      proj_body(g_Qh, g_Wh[0], WQb, (void*)g_q, 1);
    else if (z == 1) proj_body(g_Kh, g_Wh[1], WKb, (void*)g_k, 1);
    else             proj_body(g_Vh, g_Wh[2], WVb, (void*)g_vT, 2);
}

__global__ void __launch_bounds__(512, 1) proj_out(
    const float* __restrict__ Wob, float* __restrict__ out)
{
    proj_body(g_attnh, g_Wh[3], Wob, (void*)out, 0);
}

// ---------------------------------------------------------------------------
// Fused attention: 128-key staged chunks, ONE __syncthreads per chunk.
// Pass A: 4-buffer ring (depth 2 outstanding).  Pass B: K+V double-buffered.
// ---------------------------------------------------------------------------
#define NCH2 16
#define BUFW 5120
#define FA_SMEM_BYTES (4*BUFW*4)   // 81920

__global__ void __launch_bounds__(256, 2) fused_attn(float* __restrict__ P)
{
    extern __shared__ uint32_t sm[];
    const int tid = threadIdx.x;
    const int lane = tid & 31, warp = tid >> 5;
    const int g = lane >> 2, t = lane & 3;
    const int bh = blockIdx.y;
    const int i0 = blockIdx.x * 128;
    const int b_ = bh >> 4, h = bh & 15;
    const int wm = warp * 16;
    const int row0 = i0 + wm + g;

    const uint32_t* Kg = g_k + (size_t)bh * SSEQ * 32;
    const uint32_t* Vg = g_vT + (size_t)bh * DK * 1024;
    float* Pg = P + (size_t)bh * SSEQ * SSEQ;
    const uint32_t* mb0 = g_mbits + ((size_t)b_ * SSEQ + row0) * 64;
    const uint32_t* mb1 = mb0 + (size_t)8 * 64;

    const uint32_t sbase = (uint32_t)__cvta_generic_to_shared(sm);

    auto stageK_to = [&](int c, int buf) {
        const uint32_t dbase = sbase + (uint32_t)(buf * BUFW) * 4;
        const uint32_t* src = Kg + (size_t)c * 4096;
#pragma unroll
        for (int s = 0; s < 4; s++) {
            const int idx = tid + s * 256;
            const int key = idx >> 3, seg = idx & 7;
            cp16(dbase + (uint32_t)(key * 40 + seg * 4) * 4, src + key * 32 + seg * 4);
        }
    };
    auto stageV_to = [&](int c, int buf) {
        const uint32_t dbase = sbase + (uint32_t)(buf * BUFW) * 4;
#pragma unroll
        for (int s = 0; s < 4; s++) {
            const int idx = tid + s * 256;
            const int d = idx >> 4, seg = idx & 15;
            cp16(dbase + (uint32_t)(d * 72 + seg * 4) * 4,
                 Vg + (size_t)d * 1024 + c * 64 + seg * 4);
        }
    };

    uint32_t qf[4][4];
#pragma unroll
    for (int ks = 0; ks < 4; ks++) {
        const uint2 qa = *(const uint2*)&g_q[((size_t)bh * SSEQ + row0) * 32 + ks * 8 + 2 * t];
        const uint2 qb = *(const uint2*)&g_q[((size_t)bh * SSEQ + row0 + 8) * 32 + ks * 8 + 2 * t];
        qf[ks][0] = qa.x; qf[ks][2] = qa.y;
        qf[ks][1] = qb.x; qf[ks][3] = qb.y;
    }

    auto qk_half = [&](const uint32_t* Kb, int half, float cc[8][4]) {
#pragma unroll
        for (int ks = 0; ks < 4; ks++) {
            const int kb = ks * 8 + 2 * t;
#pragma unroll
            for (int nt = 0; nt < 8; nt++) {
                const uint2 kv = *(const uint2*)&Kb[(half * 64 + nt * 8 + g) * 40 + kb];
                uint32_t bb[2] = { kv.x, kv.y };
                mma_f16(cc[nt], qf[ks], bb);
            }
        }
    };

    // ================= PASS A: row sums (4-buffer ring, 1 sync/chunk) ======
    float l0 = 0.f, l1 = 0.f;
    stageK_to(0, 0); cp_commit();
    stageK_to(1, 1); cp_commit();
    stageK_to(2, 2); cp_commit();
    for (int c = 0; c < NCH2; c++) {
        if (c <= 13) cp_wait<2>();
        else if (c == 14) cp_wait<1>();
        else cp_wait<0>();
        __syncthreads();
        if (c + 3 < NCH2) { stageK_to(c + 3, (c + 3) & 3); cp_commit(); }
        const uint32_t* Kb = sm + (c & 3) * BUFW;
#pragma unroll
        for (int half = 0; half < 2; half++) {
            float cc[8][4] = {};
            qk_half(Kb, half, cc);
            const uint2 w0 = *(const uint2*)(mb0 + c * 4 + half * 2);
            const uint2 w1 = *(const uint2*)(mb1 + c * 4 + half * 2);
            if ((w0.x | w0.y | w1.x | w1.y) == 0u) {
#pragma unroll
                for (int nt = 0; nt < 8; nt++) {
                    l0 += exp2f(cc[nt][0] * EXPC) + exp2f(cc[nt][1] * EXPC);
                    l1 += exp2f(cc[nt][2] * EXPC) + exp2f(cc[nt][3] * EXPC);
                }
            } else {
#pragma unroll
                for (int nt = 0; nt < 8; nt++) {
                    const int sh = (nt * 8) & 31;
                    const uint32_t m0w = (nt < 4) ? w0.x : w0.y;
                    const uint32_t m1w = (nt < 4) ? w1.x : w1.y;
                    l0 += ((m0w >> (sh + 2 * t))     & 1) ? 0.f : exp2f(cc[nt][0] * EXPC);
                    l0 += ((m0w >> (sh + 2 * t + 1)) & 1) ? 0.f : exp2f(cc[nt][1] * EXPC);
                    l1 += ((m1w >> (sh + 2 * t))     & 1) ? 0.f : exp2f(cc[nt][2] * EXPC);
                    l1 += ((m1w >> (sh + 2 * t + 1)) & 1) ? 0.f : exp2f(cc[nt][3] * EXPC);
                }
            }
        }
    }
    l0 += __shfl_xor_sync(0xffffffffu, l0, 1);
    l0 += __shfl_xor_sync(0xffffffffu, l0, 2);
    l1 += __shfl_xor_sync(0xffffffffu, l1, 1);
    l1 += __shfl_xor_sync(0xffffffffu, l1, 2);
    const float inv0 = 1.f / l0, inv1 = 1.f / l1;

    __syncthreads();   // all warps done with pass-A buffers before pass B stages

    // ================= PASS B: normalize + write P + PV (1 sync/chunk) ====
    float oacc[8][4] = {};
    stageK_to(0, 0); stageV_to(0, 2); cp_commit();
    for (int c = 0; c < NCH2; c++) {
        cp_wait<0>();
        __syncthreads();
        if (c + 1 < NCH2) {
            stageK_to(c + 1, (c + 1) & 1);
            stageV_to(c + 1, 2 + ((c + 1) & 1));
            cp_commit();
        }
        const uint32_t* Kb = sm + (c & 1) * BUFW;
        const uint32_t* Vb = sm + (2 + (c & 1)) * BUFW;
#pragma unroll
        for (int half = 0; half < 2; half++) {
            float cc[8][4] = {};
            qk_half(Kb, half, cc);
            const int jc = c * 128 + half * 64;
            float* pr0 = &Pg[(size_t)row0 * SSEQ + jc + 2 * t];
            float* pr1 = &Pg[(size_t)(row0 + 8) * SSEQ + jc + 2 * t];
            const uint2 w0 = *(const uint2*)(mb0 + c * 4 + half * 2);
            const uint2 w1 = *(const uint2*)(mb1 + c * 4 + half * 2);
            if ((w0.x | w0.y | w1.x | w1.y) == 0u) {
#pragma unroll
                for (int nt = 0; nt < 8; nt++) {
                    cc[nt][0] = exp2f(cc[nt][0] * EXPC) * inv0;
                    cc[nt][1] = exp2f(cc[nt][1] * EXPC) * inv0;
                    cc[nt][2] = exp2f(cc[nt][2] * EXPC) * inv1;
                    cc[nt][3] = exp2f(cc[nt][3] * EXPC) * inv1;
                    *(float2*)&pr0[nt * 8] = make_float2(cc[nt][0], cc[nt][1]);
                    *(float2*)&pr1[nt * 8] = make_float2(cc[nt][2], cc[nt][3]);
                }
            } else {
#pragma unroll
                for (int nt = 0; nt < 8; nt++) {
                    const int sh = (nt * 8) & 31;
                    const uint32_t m0w = (nt < 4) ? w0.x : w0.y;
                    const uint32_t m1w = (nt < 4) ? w1.x : w1.y;
                    cc[nt][0] = ((m0w >> (sh + 2 * t))     & 1) ? 0.f : exp2f(cc[nt][0] * EXPC) * inv0;
                    cc[nt][1] = ((m0w >> (sh + 2 * t + 1)) & 1) ? 0.f : exp2f(cc[nt][1] * EXPC) * inv0;
                    cc[nt][2] = ((m1w >> (sh + 2 * t))     & 1) ? 0.f : exp2f(cc[nt][2] * EXPC) * inv1;
                    cc[nt][3] = ((m1w >> (sh + 2 * t + 1)) & 1) ? 0.f : exp2f(cc[nt][3] * EXPC) * inv1;
                    *(float2*)&pr0[nt * 8] = make_float2(cc[nt][0], cc[nt][1]);
                    *(float2*)&pr1[nt * 8] = make_float2(cc[nt][2], cc[nt][3]);
                }
            }
#pragma unroll
            for (int ks = 0; ks < 4; ks++) {
                uint32_t a[4] = {
                    h2pack(cc[2*ks][0],   cc[2*ks][1]),
                    h2pack(cc[2*ks][2],   cc[2*ks][3]),
                    h2pack(cc[2*ks+1][0], cc[2*ks+1][1]),
                    h2pack(cc[2*ks+1][2], cc[2*ks+1][3])
                };
                const int kb = half * 32 + ks * 8 + 2 * t;
#pragma unroll
                for (int nt = 0; nt < 8; nt++) {
                    const uint2 vv = *(const uint2*)&Vb[(nt * 8 + g) * 72 + kb];
                    uint32_t bb[2] = { vv.x, vv.y };
                    mma_f16(oacc[nt], a, bb);
                }
            }
        }
    }

    // epilogue: packed merged attn
#pragma unroll
    for (int nt = 0; nt < 8; nt++) {
        const int widx = (h * 4 + (nt >> 1)) * 8 + 2 * t + (nt & 1);
        g_attnh[((size_t)(b_ * SSEQ + row0)) * 512 + widx]     = h2pack(oacc[nt][0], oacc[nt][1]);
        g_attnh[((size_t)(b_ * SSEQ + row0 + 8)) * 512 + widx] = h2pack(oacc[nt][2], oacc[nt][3]);
    }
}

// ---------------------------------------------------------------------------
extern "C" void kernel_launch(void* const* d_in, const int* in_sizes, int n_in,
                              void* d_out, int out_size)
{
    const float* Q   = (const float*)d_in[0];
    const float* K   = (const float*)d_in[1];
    const float* V   = (const float*)d_in[2];
    const unsigned char* mask = (const unsigned char*)d_in[3];
    const float* WQw = (const float*)d_in[4];
    const float* WQb = (const float*)d_in[5];
    const float* WKw = (const float*)d_in[6];
    const float* WKb = (const float*)d_in[7];
    const float* WVw = (const float*)d_in[8];
    const float* WVb = (const float*)d_in[9];
    const float* Wow = (const float*)d_in[10];
    const float* Wob = (const float*)d_in[11];

    float* out   = (float*)d_out;                       // [B,S,D]
    float* attnw = out + (size_t)MTOT * DM;             // [B,H,S,S]

    cudaFuncSetAttribute(fused_attn, cudaFuncAttributeMaxDynamicSharedMemorySize,
                         FA_SMEM_BYTES);
    cudaFuncSetAttribute(proj_qkv, cudaFuncAttributeMaxDynamicSharedMemorySize,
                         PJ_SMEM_BYTES);
    cudaFuncSetAttribute(proj_out, cudaFuncAttributeMaxDynamicSharedMemorySize,
                         PJ_SMEM_BYTES);

    pack_all<<<5120, 256>>>(Q, K, V, WQw, WKw, WVw, Wow, mask);

    proj_qkv<<<dim3(8, 16, 3), 512, PJ_SMEM_BYTES>>>(WQb, WKb, WVb);

    fused_attn<<<dim3(16, 32), 256, FA_SMEM_BYTES>>>(attnw);

    proj_out<<<dim3(8, 16), 512, PJ_SMEM_BYTES>>>(Wob, out);
}

// round 16
// speedup vs baseline: 2.2004x; 1.0038x over previous
#include <cuda_runtime.h>
#include <cuda_fp16.h>
#include <cstdint>
#include <cstddef>

#define DM 1024
#define NH 16
#define DK 64
#define BB 2
#define SSEQ 2048
#define MTOT (BB*SSEQ)     // 4096
#define BH (BB*NH)         // 32

#define EXPC 0.18033688011112042f   // 0.125 * log2(e)

// Packed half2 words (uint32), k/d sigma-paired within 8-word (16-half) groups.
__device__ uint32_t g_Qh[(size_t)MTOT*512];
__device__ uint32_t g_Kh[(size_t)MTOT*512];
__device__ uint32_t g_Vh[(size_t)MTOT*512];
__device__ uint32_t g_Wh[4][(size_t)DM*512];
__device__ uint32_t g_q[(size_t)BH*SSEQ*32];   // projected q [bh][s][32w]
__device__ uint32_t g_k[(size_t)BH*SSEQ*32];
__device__ uint32_t g_vT[(size_t)BH*DK*1024];  // [bh][64 d][1024w keys sigma'd]
__device__ uint32_t g_attnh[(size_t)MTOT*512]; // merged attn, packed
__device__ uint32_t g_mbits[(size_t)BB*SSEQ*(SSEQ/32)];

// ---------------------------------------------------------------------------
__device__ __forceinline__ uint32_t h2pack(float a, float b) {
    __half2 h = __floats2half2_rn(a, b);
    return *(uint32_t*)&h;
}
__device__ __forceinline__ void mma_f16(float* c, const uint32_t* a, const uint32_t* b) {
    asm volatile(
        "mma.sync.aligned.m16n8k16.row.col.f32.f16.f16.f32 "
        "{%0,%1,%2,%3}, {%4,%5,%6,%7}, {%8,%9}, {%0,%1,%2,%3};\n"
        : "+f"(c[0]), "+f"(c[1]), "+f"(c[2]), "+f"(c[3])
        : "r"(a[0]), "r"(a[1]), "r"(a[2]), "r"(a[3]), "r"(b[0]), "r"(b[1]));
}
__device__ __forceinline__ void cp16(uint32_t d, const void* s) {
    asm volatile("cp.async.ca.shared.global [%0], [%1], 16;\n" :: "r"(d), "l"(s));
}
__device__ __forceinline__ void cp_commit() { asm volatile("cp.async.commit_group;\n"); }
template<int N> __device__ __forceinline__ void cp_wait() {
    asm volatile("cp.async.wait_group %0;\n" :: "n"(N));
}
__device__ __host__ __forceinline__ int sigma8(int j) {
    return (j < 4) ? 2 * j : 2 * (j - 4) + 1;
}

// ---------------------------------------------------------------------------
// pack_all: blocks [0,4096) pack Q,K,V,W*; blocks [4096,5120) build maskbits.
// ---------------------------------------------------------------------------
__global__ void pack_all(const float* __restrict__ Q, const float* __restrict__ K,
                         const float* __restrict__ V, const float* __restrict__ WQ,
                         const float* __restrict__ WK, const float* __restrict__ WV,
                         const float* __restrict__ Wo, const unsigned char* __restrict__ mask)
{
    const int blk = blockIdx.x;
    if (blk >= 4096) {
        const int idx = (blk - 4096) * 256 + threadIdx.x;
        const uint32_t* src = (const uint32_t*)(mask + (size_t)idx * 32);
        uint32_t w = 0;
#pragma unroll
        for (int q = 0; q < 8; q++) {
            const uint32_t v = src[q];
            if (v & 0x000000ffu) w |= 1u << (q * 4 + 0);
            if (v & 0x0000ff00u) w |= 1u << (q * 4 + 1);
            if (v & 0x00ff0000u) w |= 1u << (q * 4 + 2);
            if (v & 0xff000000u) w |= 1u << (q * 4 + 3);
        }
        g_mbits[idx] = w;
        return;
    }
    const float* src; uint32_t* dst; int base;
    if      (blk < 1024) { src = Q;  dst = g_Qh;    base = blk; }
    else if (blk < 2048) { src = K;  dst = g_Kh;    base = blk - 1024; }
    else if (blk < 3072) { src = V;  dst = g_Vh;    base = blk - 2048; }
    else if (blk < 3328) { src = WQ; dst = g_Wh[0]; base = blk - 3072; }
    else if (blk < 3584) { src = WK; dst = g_Wh[1]; base = blk - 3328; }
    else if (blk < 3840) { src = WV; dst = g_Wh[2]; base = blk - 3584; }
    else                 { src = Wo; dst = g_Wh[3]; base = blk - 3840; }
    const int idx = base * 256 + threadIdx.x;
    const float* s = src + (size_t)idx * 16;
    uint32_t w[8];
#pragma unroll
    for (int j = 0; j < 8; j++) {
        const float2 v = *(const float2*)(s + 2 * j);
        w[j] = h2pack(v.x, v.y);
    }
    uint4* d = (uint4*)(dst + (size_t)idx * 8);
    d[0] = make_uint4(w[0], w[4], w[1], w[5]);
    d[1] = make_uint4(w[2], w[6], w[3], w[7]);
}

// ---------------------------------------------------------------------------
// Projection GEMM: M=256 x N=128 tile, 512 threads (16 warps = 8m x 2n),
// warp tile 32x64, per-thread tile identical to R12 (bit-identical results).
// Dynamic smem: A bufs 2x5120w, B bufs 2x2560w = 61440 B.
// ---------------------------------------------------------------------------
#define PW 20
#define PJ_SMEM_W 15360
#define PJ_SMEM_BYTES (PJ_SMEM_W*4)

__device__ __forceinline__ void proj_body(
    const uint32_t* __restrict__ Ah, const uint32_t* __restrict__ Wh,
    const float* __restrict__ bias, void* __restrict__ outv, int mode)
{
    extern __shared__ uint32_t psm[];
    const int tid = threadIdx.x;
    const int m0 = blockIdx.y * 256, n0 = blockIdx.x * 128;
    const int lane = tid & 31, warp = tid >> 5;
    const int wm = (warp & 7) * 32, wn = (warp >> 3) * 64;
    const int g = lane >> 2, t = lane & 3;

    const uint32_t sbase = (uint32_t)__cvta_generic_to_shared(psm);
    // A staging: 256 rows x 16 words, thread -> (row = tid>>1, e = tid&1)
    const int arow = tid >> 1, ae = tid & 1;
    const uint32_t* Asrc = Ah + (size_t)(m0 + arow) * 512 + ae * 8;
    const uint32_t dAb = sbase + (uint32_t)(arow * PW + ae * 8) * 4;
    // B staging: 128 rows x 16 words, thread -> (row = tid>>2, seg = tid&3)
    const int brow = tid >> 2, bseg = tid & 3;
    const uint32_t* Wsrc = Wh + (size_t)(n0 + brow) * 512 + bseg * 4;
    const uint32_t dBb = sbase + (uint32_t)(10240 + brow * PW + bseg * 4) * 4;

    auto stage = [&](int tile, int buf) {
        const uint32_t aoff = (uint32_t)(buf * 5120) * 4;
        const uint32_t boff = (uint32_t)(buf * 2560) * 4;
        cp16(dAb + aoff, Asrc + tile * 16);
        cp16(dAb + aoff + 16, Asrc + tile * 16 + 4);
        cp16(dBb + boff, Wsrc + tile * 16);
    };

    float c[2][8][4] = {};

    stage(0, 0); cp_commit();
    for (int tl = 0; tl < 32; tl++) {
        cp_wait<0>();
        __syncthreads();
        if (tl + 1 < 32) { stage(tl + 1, (tl + 1) & 1); cp_commit(); }
        const uint32_t* As = psm + (tl & 1) * 5120;
        const uint32_t* Bs = psm + 10240 + (tl & 1) * 2560;
#pragma unroll
        for (int ks = 0; ks < 2; ks++) {
            const int kb = ks * 8 + 2 * t;
            uint32_t af[2][4], bf[8][2];
#pragma unroll
            for (int mi = 0; mi < 2; mi++) {
                const int r = wm + mi * 16 + g;
                const uint2 x = *(const uint2*)&As[r * PW + kb];
                const uint2 y = *(const uint2*)&As[(r + 8) * PW + kb];
                af[mi][0] = x.x; af[mi][2] = x.y;
                af[mi][1] = y.x; af[mi][3] = y.y;
            }
#pragma unroll
            for (int ni = 0; ni < 8; ni++) {
                const uint2 z = *(const uint2*)&Bs[(wn + ni * 8 + g) * PW + kb];
                bf[ni][0] = z.x; bf[ni][1] = z.y;
            }
#pragma unroll
            for (int mi = 0; mi < 2; mi++)
#pragma unroll
                for (int ni = 0; ni < 8; ni++)
                    mma_f16(c[mi][ni], af[mi], bf[ni]);
        }
        __syncthreads();
    }

#pragma unroll
    for (int mi = 0; mi < 2; mi++) {
#pragma unroll
        for (int rr = 0; rr < 2; rr++) {
            const int m = m0 + wm + mi * 16 + g + rr * 8;
            const int b_ = m >> 11, s = m & 2047;
#pragma unroll
            for (int ni = 0; ni < 8; ni++) {
                const int n = n0 + wn + ni * 8 + 2 * t;
                const float v0 = c[mi][ni][rr * 2 + 0] + bias[n];
                const float v1 = c[mi][ni][rr * 2 + 1] + bias[n + 1];
                if (mode == 0) {
                    *(float2*)&((float*)outv)[(size_t)m * 1024 + n] = make_float2(v0, v1);
                } else if (mode == 1) {
                    const int h = n >> 6;
                    const int ni_l = (n & 63) >> 3;
                    const int widx = (ni_l >> 1) * 8 + 2 * t + (ni_l & 1);
                    ((uint32_t*)outv)[((size_t)(b_ * 16 + h) * 2048 + s) * 32 + widx] =
                        h2pack(v0, v1);
                } else {
                    const int h = n >> 6;
                    const int dn = n & 63;
                    const int sw = (s >> 4) * 16 + sigma8((s & 15) >> 1) * 2 + (s & 1);
                    __half* vh = (__half*)outv;
                    vh[((size_t)(b_ * 16 + h) * 64 + dn) * 2048 + sw]     = __float2half_rn(v0);
                    vh[((size_t)(b_ * 16 + h) * 64 + dn + 1) * 2048 + sw] = __float2half_rn(v1);
                }
            }
        }
    }
}

__global__ void __launch_bounds__(512, 1) proj_qkv(
    const float* __restrict__ WQb, const float* __restrict__ WKb,
    const float* __restrict__ WVb)
{
    const int z = blockIdx.z;
    if (z == 0)      proj_body(g_Qh, g_Wh[0], WQb, (void*)g_q, 1);
    else if (z == 1) proj_body(g_Kh, g_Wh[1], WKb, (void*)g_k, 1);
    else             proj_body(g_Vh, g_Wh[2], WVb, (void*)g_vT, 2);
}

__global__ void __launch_bounds__(512, 1) proj_out(
    const float* __restrict__ Wob, float* __restrict__ out)
{
    proj_body(g_attnh, g_Wh[3], Wob, (void*)out, 0);
}

// ---------------------------------------------------------------------------
// Fused attention: 128-key staged chunks, ONE __syncthreads per chunk.
// Pass A: 4-buffer ring (depth 2 outstanding).  Pass B: K+V double-buffered.
// ---------------------------------------------------------------------------
#define NCH2 16
#define BUFW 5120
#define FA_SMEM_BYTES (4*BUFW*4)   // 81920

__global__ void __launch_bounds__(256, 2) fused_attn(float* __restrict__ P)
{
    extern __shared__ uint32_t sm[];
    const int tid = threadIdx.x;
    const int lane = tid & 31, warp = tid >> 5;
    const int g = lane >> 2, t = lane & 3;
    const int bh = blockIdx.y;
    const int i0 = blockIdx.x * 128;
    const int b_ = bh >> 4, h = bh & 15;
    const int wm = warp * 16;
    const int row0 = i0 + wm + g;

    const uint32_t* Kg = g_k + (size_t)bh * SSEQ * 32;
    const uint32_t* Vg = g_vT + (size_t)bh * DK * 1024;
    float* Pg = P + (size_t)bh * SSEQ * SSEQ;
    const uint32_t* mb0 = g_mbits + ((size_t)b_ * SSEQ + row0) * 64;
    const uint32_t* mb1 = mb0 + (size_t)8 * 64;

    const uint32_t sbase = (uint32_t)__cvta_generic_to_shared(sm);

    auto stageK_to = [&](int c, int buf) {
        const uint32_t dbase = sbase + (uint32_t)(buf * BUFW) * 4;
        const uint32_t* src = Kg + (size_t)c * 4096;
#pragma unroll
        for (int s = 0; s < 4; s++) {
            const int idx = tid + s * 256;
            const int key = idx >> 3, seg = idx & 7;
            cp16(dbase + (uint32_t)(key * 40 + seg * 4) * 4, src + key * 32 + seg * 4);
        }
    };
    auto stageV_to = [&](int c, int buf) {
        const uint32_t dbase = sbase + (uint32_t)(buf * BUFW) * 4;
#pragma unroll
        for (int s = 0; s < 4; s++) {
            const int idx = tid + s * 256;
            const int d = idx >> 4, seg = idx & 15;
            cp16(dbase + (uint32_t)(d * 72 + seg * 4) * 4,
                 Vg + (size_t)d * 1024 + c * 64 + seg * 4);
        }
    };

    uint32_t qf[4][4];
#pragma unroll
    for (int ks = 0; ks < 4; ks++) {
        const uint2 qa = *(const uint2*)&g_q[((size_t)bh * SSEQ + row0) * 32 + ks * 8 + 2 * t];
        const uint2 qb = *(const uint2*)&g_q[((size_t)bh * SSEQ + row0 + 8) * 32 + ks * 8 + 2 * t];
        qf[ks][0] = qa.x; qf[ks][2] = qa.y;
        qf[ks][1] = qb.x; qf[ks][3] = qb.y;
    }

    auto qk_half = [&](const uint32_t* Kb, int half, float cc[8][4]) {
#pragma unroll
        for (int ks = 0; ks < 4; ks++) {
            const int kb = ks * 8 + 2 * t;
#pragma unroll
            for (int nt = 0; nt < 8; nt++) {
                const uint2 kv = *(const uint2*)&Kb[(half * 64 + nt * 8 + g) * 40 + kb];
                uint32_t bb[2] = { kv.x, kv.y };
                mma_f16(cc[nt], qf[ks], bb);
            }
        }
    };

    // ================= PASS A: row sums (4-buffer ring, 1 sync/chunk) ======
    float l0 = 0.f, l1 = 0.f;
    stageK_to(0, 0); cp_commit();
    stageK_to(1, 1); cp_commit();
    stageK_to(2, 2); cp_commit();
    for (int c = 0; c < NCH2; c++) {
        if (c <= 13) cp_wait<2>();
        else if (c == 14) cp_wait<1>();
        else cp_wait<0>();
        __syncthreads();
        if (c + 3 < NCH2) { stageK_to(c + 3, (c + 3) & 3); cp_commit(); }
        const uint32_t* Kb = sm + (c & 3) * BUFW;
#pragma unroll
        for (int half = 0; half < 2; half++) {
            float cc[8][4] = {};
            qk_half(Kb, half, cc);
            const uint2 w0 = *(const uint2*)(mb0 + c * 4 + half * 2);
            const uint2 w1 = *(const uint2*)(mb1 + c * 4 + half * 2);
            if ((w0.x | w0.y | w1.x | w1.y) == 0u) {
#pragma unroll
                for (int nt = 0; nt < 8; nt++) {
                    l0 += exp2f(cc[nt][0] * EXPC) + exp2f(cc[nt][1] * EXPC);
                    l1 += exp2f(cc[nt][2] * EXPC) + exp2f(cc[nt][3] * EXPC);
                }
            } else {
#pragma unroll
                for (int nt = 0; nt < 8; nt++) {
                    const int sh = (nt * 8) & 31;
                    const uint32_t m0w = (nt < 4) ? w0.x : w0.y;
                    const uint32_t m1w = (nt < 4) ? w1.x : w1.y;
                    l0 += ((m0w >> (sh + 2 * t))     & 1) ? 0.f : exp2f(cc[nt][0] * EXPC);
                    l0 += ((m0w >> (sh + 2 * t + 1)) & 1) ? 0.f : exp2f(cc[nt][1] * EXPC);
                    l1 += ((m1w >> (sh + 2 * t))     & 1) ? 0.f : exp2f(cc[nt][2] * EXPC);
                    l1 += ((m1w >> (sh + 2 * t + 1)) & 1) ? 0.f : exp2f(cc[nt][3] * EXPC);
                }
            }
        }
    }
    l0 += __shfl_xor_sync(0xffffffffu, l0, 1);
    l0 += __shfl_xor_sync(0xffffffffu, l0, 2);
    l1 += __shfl_xor_sync(0xffffffffu, l1, 1);
    l1 += __shfl_xor_sync(0xffffffffu, l1, 2);
    const float inv0 = 1.f / l0, inv1 = 1.f / l1;

    __syncthreads();   // all warps done with pass-A buffers before pass B stages

    // ================= PASS B: normalize + write P + PV (1 sync/chunk) ====
    float oacc[8][4] = {};
    stageK_to(0, 0); stageV_to(0, 2); cp_commit();
    for (int c = 0; c < NCH2; c++) {
        cp_wait<0>();
        __syncthreads();
        if (c + 1 < NCH2) {
            stageK_to(c + 1, (c + 1) & 1);
            stageV_to(c + 1, 2 + ((c + 1) & 1));
            cp_commit();
        }
        const uint32_t* Kb = sm + (c & 1) * BUFW;
        const uint32_t* Vb = sm + (2 + (c & 1)) * BUFW;
#pragma unroll
        for (int half = 0; half < 2; half++) {
            float cc[8][4] = {};
            qk_half(Kb, half, cc);
            const int jc = c * 128 + half * 64;
            float* pr0 = &Pg[(size_t)row0 * SSEQ + jc + 2 * t];
            float* pr1 = &Pg[(size_t)(row0 + 8) * SSEQ + jc + 2 * t];
            const uint2 w0 = *(const uint2*)(mb0 + c * 4 + half * 2);
            const uint2 w1 = *(const uint2*)(mb1 + c * 4 + half * 2);
            if ((w0.x | w0.y | w1.x | w1.y) == 0u) {
#pragma unroll
                for (int nt = 0; nt < 8; nt++) {
                    cc[nt][0] = exp2f(cc[nt][0] * EXPC) * inv0;
                    cc[nt][1] = exp2f(cc[nt][1] * EXPC) * inv0;
                    cc[nt][2] = exp2f(cc[nt][2] * EXPC) * inv1;
                    cc[nt][3] = exp2f(cc[nt][3] * EXPC) * inv1;
                    *(float2*)&pr0[nt * 8] = make_float2(cc[nt][0], cc[nt][1]);
                    *(float2*)&pr1[nt * 8] = make_float2(cc[nt][2], cc[nt][3]);
                }
            } else {
#pragma unroll
                for (int nt = 0; nt < 8; nt++) {
                    const int sh = (nt * 8) & 31;
                    const uint32_t m0w = (nt < 4) ? w0.x : w0.y;
                    const uint32_t m1w = (nt < 4) ? w1.x : w1.y;
                    cc[nt][0] = ((m0w >> (sh + 2 * t))     & 1) ? 0.f : exp2f(cc[nt][0] * EXPC) * inv0;
                    cc[nt][1] = ((m0w >> (sh + 2 * t + 1)) & 1) ? 0.f : exp2f(cc[nt][1] * EXPC) * inv0;
                    cc[nt][2] = ((m1w >> (sh + 2 * t))     & 1) ? 0.f : exp2f(cc[nt][2] * EXPC) * inv1;
                    cc[nt][3] = ((m1w >> (sh + 2 * t + 1)) & 1) ? 0.f : exp2f(cc[nt][3] * EXPC) * inv1;
                    *(float2*)&pr0[nt * 8] = make_float2(cc[nt][0], cc[nt][1]);
                    *(float2*)&pr1[nt * 8] = make_float2(cc[nt][2], cc[nt][3]);
                }
            }
#pragma unroll
            for (int ks = 0; ks < 4; ks++) {
                uint32_t a[4] = {
                    h2pack(cc[2*ks][0],   cc[2*ks][1]),
                    h2pack(cc[2*ks][2],   cc[2*ks][3]),
                    h2pack(cc[2*ks+1][0], cc[2*ks+1][1]),
                    h2pack(cc[2*ks+1][2], cc[2*ks+1][3])
                };
                const int kb = half * 32 + ks * 8 + 2 * t;
#pragma unroll
                for (int nt = 0; nt < 8; nt++) {
                    const uint2 vv = *(const uint2*)&Vb[(nt * 8 + g) * 72 + kb];
                    uint32_t bb[2] = { vv.x, vv.y };
                    mma_f16(oacc[nt], a, bb);
                }
            }
        }
    }

    // epilogue: packed merged attn
#pragma unroll
    for (int nt = 0; nt < 8; nt++) {
        const int widx = (h * 4 + (nt >> 1)) * 8 + 2 * t + (nt & 1);
        g_attnh[((size_t)(b_ * SSEQ + row0)) * 512 + widx]     = h2pack(oacc[nt][0], oacc[nt][1]);
        g_attnh[((size_t)(b_ * SSEQ + row0 + 8)) * 512 + widx] = h2pack(oacc[nt][2], oacc[nt][3]);
    }
}

// ---------------------------------------------------------------------------
extern "C" void kernel_launch(void* const* d_in, const int* in_sizes, int n_in,
                              void* d_out, int out_size)
{
    const float* Q   = (const float*)d_in[0];
    const float* K   = (const float*)d_in[1];
    const float* V   = (const float*)d_in[2];
    const unsigned char* mask = (const unsigned char*)d_in[3];
    const float* WQw = (const float*)d_in[4];
    const float* WQb = (const float*)d_in[5];
    const float* WKw = (const float*)d_in[6];
    const float* WKb = (const float*)d_in[7];
    const float* WVw = (const float*)d_in[8];
    const float* WVb = (const float*)d_in[9];
    const float* Wow = (const float*)d_in[10];
    const float* Wob = (const float*)d_in[11];

    float* out   = (float*)d_out;                       // [B,S,D]
    float* attnw = out + (size_t)MTOT * DM;             // [B,H,S,S]

    cudaFuncSetAttribute(fused_attn, cudaFuncAttributeMaxDynamicSharedMemorySize,
                         FA_SMEM_BYTES);
    cudaFuncSetAttribute(proj_qkv, cudaFuncAttributeMaxDynamicSharedMemorySize,
                         PJ_SMEM_BYTES);
    cudaFuncSetAttribute(proj_out, cudaFuncAttributeMaxDynamicSharedMemorySize,
                         PJ_SMEM_BYTES);

    pack_all<<<5120, 256>>>(Q, K, V, WQw, WKw, WVw, Wow, mask);

    proj_qkv<<<dim3(8, 16, 3), 512, PJ_SMEM_BYTES>>>(WQb, WKb, WVb);

    fused_attn<<<dim3(16, 32), 256, FA_SMEM_BYTES>>>(attnw);

    proj_out<<<dim3(8, 16), 512, PJ_SMEM_BYTES>>>(Wob, out);
}